// round 2
// baseline (speedup 1.0000x reference)
#include <cuda_runtime.h>
#include <math.h>

#define BB 2
#define SS 512
#define DD 768
#define HH 12
#define NLAYER 6
#define VV 32000
#define HDIM 64
#define DFF 3072
#define EPSF 1e-6f

// ---------------- scratch (device globals; no allocs allowed) ----------------
__device__ float g_h  [BB*SS*DD];
__device__ float g_hn [BB*SS*DD];
__device__ float g_q  [BB*SS*DD];
__device__ float g_k  [BB*SS*DD];
__device__ float g_v  [BB*SS*DD];
__device__ float g_ctx[BB*SS*DD];
__device__ float g_ffn[BB*SS*DFF];
__device__ float g_sc [BB*HH*SS*SS];

// ---------------- embedding ----------------
__global__ void embed_kernel(const int* __restrict__ x, const float* __restrict__ tok,
                             const float* __restrict__ pos, float* __restrict__ out) {
    int idx = blockIdx.x * blockDim.x + threadIdx.x;
    if (idx >= BB*SS*DD) return;
    int d  = idx % DD;
    int bs = idx / DD;
    int s  = bs % SS;
    out[idx] = tok[(long long)x[bs]*DD + d] + pos[s*DD + d];
}

// ---------------- "DummyNorm": s*(x-mean)/(std_ddof1 + eps) + b ----------------
__global__ void norm_kernel(const float* __restrict__ x, const float* __restrict__ sc,
                            const float* __restrict__ bi, float* __restrict__ y) {
    int row = blockIdx.x;                 // B*S rows
    const float* xr = x + (long long)row * DD;
    float* yr = y + (long long)row * DD;
    int tid = threadIdx.x;
    float sum = 0.f, sq = 0.f;
    for (int i = tid; i < DD; i += 256) { float v = xr[i]; sum += v; sq += v*v; }
    __shared__ float s1[256], s2[256];
    s1[tid] = sum; s2[tid] = sq; __syncthreads();
    for (int st = 128; st > 0; st >>= 1) {
        if (tid < st) { s1[tid] += s1[tid+st]; s2[tid] += s2[tid+st]; }
        __syncthreads();
    }
    float mean = s1[0] / (float)DD;
    float var  = (s2[0] - (float)DD * mean * mean) / (float)(DD - 1);
    float inv  = 1.f / (sqrtf(fmaxf(var, 0.f)) + EPSF);
    for (int i = tid; i < DD; i += 256) yr[i] = sc[i] * (xr[i] - mean) * inv + bi[i];
}

// ---------------- masked+scaled softmax over key axis ----------------
// mask: strictly-lower-tri (k < q) -> -inf  => valid keys are k >= q
__global__ void softmax_kernel(float* __restrict__ scores) {
    int row = blockIdx.x;                 // b*H*S + h*S + q
    int q = row % SS;
    float* p = scores + (long long)row * SS;
    int tid = threadIdx.x;
    const float scale = 0.125f;           // 1/sqrt(64)
    float m = -1e30f;
    for (int k = q + tid; k < SS; k += 128) m = fmaxf(m, p[k] * scale);
    __shared__ float sh[128];
    sh[tid] = m; __syncthreads();
    for (int st = 64; st > 0; st >>= 1) { if (tid < st) sh[tid] = fmaxf(sh[tid], sh[tid+st]); __syncthreads(); }
    m = sh[0]; __syncthreads();
    float sum = 0.f;
    for (int k = q + tid; k < SS; k += 128) { float e = __expf(p[k]*scale - m); p[k] = e; sum += e; }
    sh[tid] = sum; __syncthreads();
    for (int st = 64; st > 0; st >>= 1) { if (tid < st) sh[tid] += sh[tid+st]; __syncthreads(); }
    float inv = 1.f / sh[0];
    for (int k = q + tid; k < SS; k += 128) p[k] *= inv;
    for (int k = tid; k < q; k += 128) p[k] = 0.f;
}

// ---------------- tiled SGEMM: 128x64 tile, 8x4 microtile, k-major smem ----------------
// C[m,n] = sum_k A[m,k] * (TRANSB ? B[n,k] : B[k,n]); optional +bias[n], GELU, +res[m,n]
// batch via blockIdx.z: zd = z / zdiv, zm = z % zdiv; base offsets zd*sX1 + zm*sX2
template<int TRANSB>
__global__ void __launch_bounds__(256)
gemm_kernel(const float* __restrict__ A, const float* __restrict__ Bm,
            const float* __restrict__ bias, const float* __restrict__ res,
            float* __restrict__ C,
            int K, int lda, int ldb, int ldc, int act, int zdiv,
            long long sa1, long long sa2, long long sb1, long long sb2,
            long long sc1, long long sc2)
{
    __shared__ float As[16][132];   // [k][m], padded
    __shared__ float Bs[16][68];    // [k][n], padded

    int z  = blockIdx.z;
    int zd = z / zdiv, zm = z % zdiv;
    const float* Ab = A  + zd*sa1 + zm*sa2;
    const float* Bb = Bm + zd*sb1 + zm*sb2;
    float*       Cb = C  + zd*sc1 + zm*sc2;
    const float* Rb = res ? (res + zd*sc1 + zm*sc2) : (const float*)0;

    int tid = threadIdx.x;                   // 256
    int tx = tid & 15;                       // n group (0..15) -> 4 cols
    int ty = tid >> 4;                       // m group (0..15) -> 8 rows
    int m0 = blockIdx.y * 128;
    int n0 = blockIdx.x * 64;

    // A-load indices: 128x16 tile = 512 float4 -> 2 per thread
    int am0 = tid >> 2;                      // row 0..63  (and +64)
    int ak0 = (tid & 3) * 4;                 // k 0,4,8,12
    // B-load indices
    int bn_t = tid >> 2;                     // TRANSB: n row 0..63
    int bk_t = (tid & 3) * 4;
    int bk_n = tid >> 4;                     // !TRANSB: k row 0..15
    int bn_n = (tid & 15) * 4;

    float acc[8][4];
    #pragma unroll
    for (int i = 0; i < 8; i++)
        #pragma unroll
        for (int j = 0; j < 4; j++) acc[i][j] = 0.f;

    for (int kt = 0; kt < K; kt += 16) {
        // ---- stage A (transpose to k-major) ----
        #pragma unroll
        for (int j = 0; j < 2; j++) {
            int m = am0 + j * 64;
            float4 a4 = *(const float4*)(Ab + (long long)(m0 + m)*lda + kt + ak0);
            As[ak0+0][m] = a4.x; As[ak0+1][m] = a4.y;
            As[ak0+2][m] = a4.z; As[ak0+3][m] = a4.w;
        }
        // ---- stage B (k-major) ----
        if (TRANSB) {
            float4 b4 = *(const float4*)(Bb + (long long)(n0 + bn_t)*ldb + kt + bk_t);
            Bs[bk_t+0][bn_t] = b4.x; Bs[bk_t+1][bn_t] = b4.y;
            Bs[bk_t+2][bn_t] = b4.z; Bs[bk_t+3][bn_t] = b4.w;
        } else {
            *(float4*)&Bs[bk_n][bn_n] =
                *(const float4*)(Bb + (long long)(kt + bk_n)*ldb + n0 + bn_n);
        }
        __syncthreads();

        #pragma unroll
        for (int k = 0; k < 16; k++) {
            float4 a0 = *(const float4*)&As[k][ty*8];
            float4 a1 = *(const float4*)&As[k][ty*8 + 4];
            float4 bv = *(const float4*)&Bs[k][tx*4];
            float am[8] = {a0.x, a0.y, a0.z, a0.w, a1.x, a1.y, a1.z, a1.w};
            #pragma unroll
            for (int i = 0; i < 8; i++) {
                acc[i][0] += am[i]*bv.x; acc[i][1] += am[i]*bv.y;
                acc[i][2] += am[i]*bv.z; acc[i][3] += am[i]*bv.w;
            }
        }
        __syncthreads();
    }

    // ---- epilogue ----
    int n = n0 + tx*4;
    float4 bv4 = {0.f,0.f,0.f,0.f};
    if (bias) bv4 = *(const float4*)(bias + n);
    #pragma unroll
    for (int i = 0; i < 8; i++) {
        int m = m0 + ty*8 + i;
        float4 v = {acc[i][0] + bv4.x, acc[i][1] + bv4.y,
                    acc[i][2] + bv4.z, acc[i][3] + bv4.w};
        if (act == 1) {
            float* pv = (float*)&v;
            #pragma unroll
            for (int j = 0; j < 4; j++) {
                float u = pv[j];
                float t = u + 0.044715f * u * u * u;
                pv[j] = 0.5f * u * (1.0f + tanhf(0.7978845608028654f * t));
            }
        }
        if (Rb) {
            float4 r4 = *(const float4*)(Rb + (long long)m*ldc + n);
            v.x += r4.x; v.y += r4.y; v.z += r4.z; v.w += r4.w;
        }
        *(float4*)(Cb + (long long)m*ldc + n) = v;
    }
}

static void launch_gemm(const float* A, const float* Bm, const float* bias, const float* res,
                        float* C, int M, int N, int K, int lda, int ldb, int ldc,
                        int act, int batch, int transB, int zdiv,
                        long long sa1, long long sa2, long long sb1, long long sb2,
                        long long sc1, long long sc2)
{
    dim3 grid(N/64, M/128, batch), blk(256);
    if (transB)
        gemm_kernel<1><<<grid, blk>>>(A, Bm, bias, res, C, K, lda, ldb, ldc, act, zdiv,
                                      sa1, sa2, sb1, sb2, sc1, sc2);
    else
        gemm_kernel<0><<<grid, blk>>>(A, Bm, bias, res, C, K, lda, ldb, ldc, act, zdiv,
                                      sa1, sa2, sb1, sb2, sc1, sc2);
}

extern "C" void kernel_launch(void* const* d_in, const int* in_sizes, int n_in,
                              void* d_out, int out_size)
{
    const int*   x   = (const int*)  d_in[0];
    const float* tok = (const float*)d_in[1];
    const float* pos = (const float*)d_in[2];
    const float* n1s = (const float*)d_in[3];
    const float* n1b = (const float*)d_in[4];
    const float* n2s = (const float*)d_in[5];
    const float* n2b = (const float*)d_in[6];
    const float* wq  = (const float*)d_in[7];
    const float* wk  = (const float*)d_in[8];
    const float* wv  = (const float*)d_in[9];
    const float* wo  = (const float*)d_in[10];
    const float* bo  = (const float*)d_in[11];
    const float* w1  = (const float*)d_in[12];
    const float* b1  = (const float*)d_in[13];
    const float* w2  = (const float*)d_in[14];
    const float* b2  = (const float*)d_in[15];
    const float* fs  = (const float*)d_in[16];
    const float* fb  = (const float*)d_in[17];
    const float* hw  = (const float*)d_in[18];
    const float* hb  = (const float*)d_in[19];
    float* out = (float*)d_out;

    float *h, *hn, *gq, *gk, *gv, *ctx, *ffn, *sc;
    cudaGetSymbolAddress((void**)&h,   g_h);
    cudaGetSymbolAddress((void**)&hn,  g_hn);
    cudaGetSymbolAddress((void**)&gq,  g_q);
    cudaGetSymbolAddress((void**)&gk,  g_k);
    cudaGetSymbolAddress((void**)&gv,  g_v);
    cudaGetSymbolAddress((void**)&ctx, g_ctx);
    cudaGetSymbolAddress((void**)&ffn, g_ffn);
    cudaGetSymbolAddress((void**)&sc,  g_sc);

    const int M = BB * SS;                         // 1024
    const long long SD  = (long long)SS * DD;      // per-batch stride in q/k/v/h
    const long long SSs = (long long)SS * SS;      // per-head stride in scores

    embed_kernel<<<(BB*SS*DD + 255)/256, 256>>>(x, tok, pos, h);

    for (int l = 0; l < NLAYER; l++) {
        norm_kernel<<<M, 256>>>(h, n1s + l*DD, n1b + l*DD, hn);

        launch_gemm(hn, wq + (long long)l*DD*DD, 0, 0, gq, M, DD, DD, DD, DD, DD, 0, 1, 0, 1, 0,0,0,0,0,0);
        launch_gemm(hn, wk + (long long)l*DD*DD, 0, 0, gk, M, DD, DD, DD, DD, DD, 0, 1, 0, 1, 0,0,0,0,0,0);
        launch_gemm(hn, wv + (long long)l*DD*DD, 0, 0, gv, M, DD, DD, DD, DD, DD, 0, 1, 0, 1, 0,0,0,0,0,0);

        // scores[b,h,q,k] = Q . K  (batched over b*H, transB)
        launch_gemm(gq, gk, 0, 0, sc, SS, SS, HDIM, DD, DD, SS, 0, BB*HH, 1, HH,
                    SD, HDIM, SD, HDIM, (long long)HH*SSs, SSs);

        softmax_kernel<<<BB*HH*SS, 128>>>(sc);

        // ctx[b,q,h,:] = P @ V  (batched over b*H)
        launch_gemm(sc, gv, 0, 0, ctx, SS, HDIM, SS, SS, DD, DD, 0, BB*HH, 0, HH,
                    (long long)HH*SSs, SSs, SD, HDIM, SD, HDIM);

        // x = res + ctx @ wo + bo
        launch_gemm(ctx, wo + (long long)l*DD*DD, bo + l*DD, h, h, M, DD, DD, DD, DD, DD, 0, 1, 0, 1, 0,0,0,0,0,0);

        norm_kernel<<<M, 256>>>(h, n2s + l*DD, n2b + l*DD, hn);

        // ffn = gelu(hn @ w1 + b1)
        launch_gemm(hn, w1 + (long long)l*DD*DFF, b1 + l*DFF, 0, ffn, M, DFF, DD, DD, DFF, DFF, 1, 1, 0, 1, 0,0,0,0,0,0);
        // x = res + ffn @ w2 + b2
        launch_gemm(ffn, w2 + (long long)l*DFF*DD, b2 + l*DD, h, h, M, DD, DFF, DFF, DD, DD, 0, 1, 0, 1, 0,0,0,0,0,0);
    }

    norm_kernel<<<M, 256>>>(h, fs, fb, hn);
    // logits = hn @ head_w + head_b
    launch_gemm(hn, hw, hb, 0, out, M, VV, DD, DD, VV, VV, 0, 1, 0, 1, 0,0,0,0,0,0);
}

// round 3
// speedup vs baseline: 1.3072x; 1.3072x over previous
#include <cuda_runtime.h>
#include <math.h>

#define BB 2
#define SS 512
#define DD 768
#define HH 12
#define NLAYER 6
#define VV 32000
#define HDIM 64
#define DFF 3072
#define EPSF 1e-6f

// ---------------- scratch (device globals; no allocs allowed) ----------------
__device__ float g_h  [BB*SS*DD];
__device__ float g_hn [BB*SS*DD];
__device__ float g_q  [BB*SS*DD];
__device__ float g_k  [BB*SS*DD];
__device__ float g_v  [BB*SS*DD];
__device__ float g_ctx[BB*SS*DD];
__device__ float g_ffn[BB*SS*DFF];
__device__ float g_sc [BB*HH*SS*SS];

// ---------------- embedding ----------------
__global__ void embed_kernel(const int* __restrict__ x, const float* __restrict__ tok,
                             const float* __restrict__ pos, float* __restrict__ out) {
    int idx = blockIdx.x * blockDim.x + threadIdx.x;
    if (idx >= BB*SS*DD) return;
    int d  = idx % DD;
    int bs = idx / DD;
    int s  = bs % SS;
    out[idx] = tok[(long long)x[bs]*DD + d] + pos[s*DD + d];
}

// ---------------- "DummyNorm": s*(x-mean)/(std_ddof1 + eps) + b ----------------
__global__ void norm_kernel(const float* __restrict__ x, const float* __restrict__ sc,
                            const float* __restrict__ bi, float* __restrict__ y) {
    int row = blockIdx.x;                 // B*S rows
    const float* xr = x + (long long)row * DD;
    float* yr = y + (long long)row * DD;
    int tid = threadIdx.x;
    float sum = 0.f, sq = 0.f;
    for (int i = tid; i < DD; i += 256) { float v = xr[i]; sum += v; sq += v*v; }
    __shared__ float s1[256], s2[256];
    s1[tid] = sum; s2[tid] = sq; __syncthreads();
    for (int st = 128; st > 0; st >>= 1) {
        if (tid < st) { s1[tid] += s1[tid+st]; s2[tid] += s2[tid+st]; }
        __syncthreads();
    }
    float mean = s1[0] / (float)DD;
    float var  = (s2[0] - (float)DD * mean * mean) / (float)(DD - 1);
    float inv  = 1.f / (sqrtf(fmaxf(var, 0.f)) + EPSF);
    for (int i = tid; i < DD; i += 256) yr[i] = sc[i] * (xr[i] - mean) * inv + bi[i];
}

// ---------------- masked+scaled softmax over key axis ----------------
// mask: strictly-lower-tri (k < q) -> -inf  => valid keys are k >= q
__global__ void softmax_kernel(float* __restrict__ scores) {
    int row = blockIdx.x;                 // b*H*S + h*S + q
    int q = row % SS;
    float* p = scores + (long long)row * SS;
    int tid = threadIdx.x;
    const float scale = 0.125f;           // 1/sqrt(64)
    float m = -1e30f;
    for (int k = q + tid; k < SS; k += 128) m = fmaxf(m, p[k] * scale);
    __shared__ float sh[128];
    sh[tid] = m; __syncthreads();
    for (int st = 64; st > 0; st >>= 1) { if (tid < st) sh[tid] = fmaxf(sh[tid], sh[tid+st]); __syncthreads(); }
    m = sh[0]; __syncthreads();
    float sum = 0.f;
    for (int k = q + tid; k < SS; k += 128) { float e = __expf(p[k]*scale - m); p[k] = e; sum += e; }
    sh[tid] = sum; __syncthreads();
    for (int st = 64; st > 0; st >>= 1) { if (tid < st) sh[tid] += sh[tid+st]; __syncthreads(); }
    float inv = 1.f / sh[0];
    for (int k = q + tid; k < SS; k += 128) p[k] *= inv;
    for (int k = tid; k < q; k += 128) p[k] = 0.f;
}

// ---------------- SGEMM: 64x64 tile, 128 threads, 8x4 microtile, double-buffered ----------------
// C[m,n] = sum_k A[m,k] * (TRANSB ? B[n,k] : B[k,n]); optional +bias[n], GELU, +res[m,n]
// B/C pointer triple selected by blockIdx.z when nsel==3 (fused QKV);
// otherwise batch via blockIdx.z: zd=z/zdiv, zm=z%zdiv with the given strides.
template<int TRANSB>
__global__ void __launch_bounds__(128)
gemm_kernel(const float* __restrict__ A,
            const float* B0, const float* B1, const float* B2,
            float* C0, float* C1, float* C2,
            const float* __restrict__ bias, const float* __restrict__ res,
            int K, int lda, int ldb, int ldc, int act, int nsel, int zdiv,
            long long sa1, long long sa2, long long sb1, long long sb2,
            long long sc1, long long sc2)
{
    __shared__ float As[2][16][68];   // [buf][k][m]
    __shared__ float Bs[2][16][68];   // [buf][k][n]

    int z = blockIdx.z;
    int psel, zd, zm;
    if (nsel > 1) { psel = z; zd = 0; zm = 0; }
    else          { psel = 0; zd = z / zdiv; zm = z % zdiv; }
    const float* Bp = (psel == 0) ? B0 : ((psel == 1) ? B1 : B2);
    float*       Cp = (psel == 0) ? C0 : ((psel == 1) ? C1 : C2);

    const float* Ab = A  + zd*sa1 + zm*sa2;
    const float* Bb = Bp + zd*sb1 + zm*sb2;
    float*       Cb = Cp + zd*sc1 + zm*sc2;
    const float* Rb = res ? (res + zd*sc1 + zm*sc2) : (const float*)0;

    int tid = threadIdx.x;            // 128
    int m0 = blockIdx.y * 64;
    int n0 = blockIdx.x * 64;

    // A load: 64 rows x 16 k = 256 float4 slots -> 2/thread
    int a_r0 = tid >> 2;              // rows 0..31 ; second slot +32
    int a_kg = (tid & 3) * 4;         // k 0,4,8,12
    // B load (non-trans): 16 k x 64 n = 256 f4 slots
    int b_k0 = tid >> 4;              // k 0..7 ; second slot +8
    int b_n4 = (tid & 15) * 4;
    // compute indices
    int tx = tid & 15;                // n group -> 4 cols
    int ty = tid >> 4;                // m group -> 8 rows

    float acc[8][4];
    #pragma unroll
    for (int i = 0; i < 8; i++)
        #pragma unroll
        for (int j = 0; j < 4; j++) acc[i][j] = 0.f;

    float4 ra0, ra1, rb0, rb1;

    // ---- prologue: load tile kt=0, stage into buf 0 ----
    ra0 = *(const float4*)(Ab + (long long)(m0 + a_r0     )*lda + a_kg);
    ra1 = *(const float4*)(Ab + (long long)(m0 + a_r0 + 32)*lda + a_kg);
    if (TRANSB) {
        rb0 = *(const float4*)(Bb + (long long)(n0 + a_r0     )*ldb + a_kg);
        rb1 = *(const float4*)(Bb + (long long)(n0 + a_r0 + 32)*ldb + a_kg);
    } else {
        rb0 = *(const float4*)(Bb + (long long)(b_k0    )*ldb + n0 + b_n4);
        rb1 = *(const float4*)(Bb + (long long)(b_k0 + 8)*ldb + n0 + b_n4);
    }
    {
        As[0][a_kg+0][a_r0] = ra0.x; As[0][a_kg+1][a_r0] = ra0.y;
        As[0][a_kg+2][a_r0] = ra0.z; As[0][a_kg+3][a_r0] = ra0.w;
        As[0][a_kg+0][a_r0+32] = ra1.x; As[0][a_kg+1][a_r0+32] = ra1.y;
        As[0][a_kg+2][a_r0+32] = ra1.z; As[0][a_kg+3][a_r0+32] = ra1.w;
        if (TRANSB) {
            Bs[0][a_kg+0][a_r0] = rb0.x; Bs[0][a_kg+1][a_r0] = rb0.y;
            Bs[0][a_kg+2][a_r0] = rb0.z; Bs[0][a_kg+3][a_r0] = rb0.w;
            Bs[0][a_kg+0][a_r0+32] = rb1.x; Bs[0][a_kg+1][a_r0+32] = rb1.y;
            Bs[0][a_kg+2][a_r0+32] = rb1.z; Bs[0][a_kg+3][a_r0+32] = rb1.w;
        } else {
            *(float4*)&Bs[0][b_k0  ][b_n4] = rb0;
            *(float4*)&Bs[0][b_k0+8][b_n4] = rb1;
        }
    }
    __syncthreads();

    int buf = 0;
    for (int kt = 0; kt < K; kt += 16) {
        bool has_next = (kt + 16) < K;
        if (has_next) {
            int kn = kt + 16;
            ra0 = *(const float4*)(Ab + (long long)(m0 + a_r0     )*lda + kn + a_kg);
            ra1 = *(const float4*)(Ab + (long long)(m0 + a_r0 + 32)*lda + kn + a_kg);
            if (TRANSB) {
                rb0 = *(const float4*)(Bb + (long long)(n0 + a_r0     )*ldb + kn + a_kg);
                rb1 = *(const float4*)(Bb + (long long)(n0 + a_r0 + 32)*ldb + kn + a_kg);
            } else {
                rb0 = *(const float4*)(Bb + (long long)(kn + b_k0    )*ldb + n0 + b_n4);
                rb1 = *(const float4*)(Bb + (long long)(kn + b_k0 + 8)*ldb + n0 + b_n4);
            }
        }
        #pragma unroll
        for (int k = 0; k < 16; k++) {
            float4 x0 = *(const float4*)&As[buf][k][ty*8];
            float4 x1 = *(const float4*)&As[buf][k][ty*8 + 4];
            float4 y  = *(const float4*)&Bs[buf][k][tx*4];
            float am[8] = {x0.x, x0.y, x0.z, x0.w, x1.x, x1.y, x1.z, x1.w};
            #pragma unroll
            for (int i = 0; i < 8; i++) {
                acc[i][0] += am[i]*y.x; acc[i][1] += am[i]*y.y;
                acc[i][2] += am[i]*y.z; acc[i][3] += am[i]*y.w;
            }
        }
        if (has_next) {
            int nb = buf ^ 1;
            As[nb][a_kg+0][a_r0] = ra0.x; As[nb][a_kg+1][a_r0] = ra0.y;
            As[nb][a_kg+2][a_r0] = ra0.z; As[nb][a_kg+3][a_r0] = ra0.w;
            As[nb][a_kg+0][a_r0+32] = ra1.x; As[nb][a_kg+1][a_r0+32] = ra1.y;
            As[nb][a_kg+2][a_r0+32] = ra1.z; As[nb][a_kg+3][a_r0+32] = ra1.w;
            if (TRANSB) {
                Bs[nb][a_kg+0][a_r0] = rb0.x; Bs[nb][a_kg+1][a_r0] = rb0.y;
                Bs[nb][a_kg+2][a_r0] = rb0.z; Bs[nb][a_kg+3][a_r0] = rb0.w;
                Bs[nb][a_kg+0][a_r0+32] = rb1.x; Bs[nb][a_kg+1][a_r0+32] = rb1.y;
                Bs[nb][a_kg+2][a_r0+32] = rb1.z; Bs[nb][a_kg+3][a_r0+32] = rb1.w;
            } else {
                *(float4*)&Bs[nb][b_k0  ][b_n4] = rb0;
                *(float4*)&Bs[nb][b_k0+8][b_n4] = rb1;
            }
            __syncthreads();
            buf = nb;
        }
    }

    // ---- epilogue ----
    int n = n0 + tx*4;
    float4 bv4 = {0.f,0.f,0.f,0.f};
    if (bias) bv4 = *(const float4*)(bias + n);
    #pragma unroll
    for (int i = 0; i < 8; i++) {
        int m = m0 + ty*8 + i;
        float4 v = {acc[i][0] + bv4.x, acc[i][1] + bv4.y,
                    acc[i][2] + bv4.z, acc[i][3] + bv4.w};
        if (act == 1) {
            float* pv = (float*)&v;
            #pragma unroll
            for (int j = 0; j < 4; j++) {
                float u = pv[j];
                float t = u + 0.044715f * u * u * u;
                pv[j] = 0.5f * u * (1.0f + tanhf(0.7978845608028654f * t));
            }
        }
        if (Rb) {
            float4 r4 = *(const float4*)(Rb + (long long)m*ldc + n);
            v.x += r4.x; v.y += r4.y; v.z += r4.z; v.w += r4.w;
        }
        *(float4*)(Cb + (long long)m*ldc + n) = v;
    }
}

static void launch_gemm_full(const float* A,
                             const float* B0, const float* B1, const float* B2,
                             float* C0, float* C1, float* C2,
                             const float* bias, const float* res,
                             int M, int N, int K, int lda, int ldb, int ldc,
                             int act, int batch, int transB, int nsel, int zdiv,
                             long long sa1, long long sa2, long long sb1, long long sb2,
                             long long sc1, long long sc2)
{
    dim3 grid(N/64, M/64, batch), blk(128);
    if (transB)
        gemm_kernel<1><<<grid, blk>>>(A, B0,B1,B2, C0,C1,C2, bias, res, K, lda, ldb, ldc,
                                      act, nsel, zdiv, sa1, sa2, sb1, sb2, sc1, sc2);
    else
        gemm_kernel<0><<<grid, blk>>>(A, B0,B1,B2, C0,C1,C2, bias, res, K, lda, ldb, ldc,
                                      act, nsel, zdiv, sa1, sa2, sb1, sb2, sc1, sc2);
}

static void launch_gemm(const float* A, const float* Bm, const float* bias, const float* res,
                        float* C, int M, int N, int K, int lda, int ldb, int ldc,
                        int act, int batch, int transB, int zdiv,
                        long long sa1, long long sa2, long long sb1, long long sb2,
                        long long sc1, long long sc2)
{
    launch_gemm_full(A, Bm, Bm, Bm, C, C, C, bias, res, M, N, K, lda, ldb, ldc,
                     act, batch, transB, 1, zdiv, sa1, sa2, sb1, sb2, sc1, sc2);
}

extern "C" void kernel_launch(void* const* d_in, const int* in_sizes, int n_in,
                              void* d_out, int out_size)
{
    const int*   x   = (const int*)  d_in[0];
    const float* tok = (const float*)d_in[1];
    const float* pos = (const float*)d_in[2];
    const float* n1s = (const float*)d_in[3];
    const float* n1b = (const float*)d_in[4];
    const float* n2s = (const float*)d_in[5];
    const float* n2b = (const float*)d_in[6];
    const float* wq  = (const float*)d_in[7];
    const float* wk  = (const float*)d_in[8];
    const float* wv  = (const float*)d_in[9];
    const float* wo  = (const float*)d_in[10];
    const float* bo  = (const float*)d_in[11];
    const float* w1  = (const float*)d_in[12];
    const float* b1  = (const float*)d_in[13];
    const float* w2  = (const float*)d_in[14];
    const float* b2  = (const float*)d_in[15];
    const float* fs  = (const float*)d_in[16];
    const float* fb  = (const float*)d_in[17];
    const float* hw  = (const float*)d_in[18];
    const float* hb  = (const float*)d_in[19];
    float* out = (float*)d_out;

    float *h, *hn, *gq, *gk, *gv, *ctx, *ffn, *sc;
    cudaGetSymbolAddress((void**)&h,   g_h);
    cudaGetSymbolAddress((void**)&hn,  g_hn);
    cudaGetSymbolAddress((void**)&gq,  g_q);
    cudaGetSymbolAddress((void**)&gk,  g_k);
    cudaGetSymbolAddress((void**)&gv,  g_v);
    cudaGetSymbolAddress((void**)&ctx, g_ctx);
    cudaGetSymbolAddress((void**)&ffn, g_ffn);
    cudaGetSymbolAddress((void**)&sc,  g_sc);

    const int M = BB * SS;                         // 1024
    const long long SD  = (long long)SS * DD;      // per-batch stride in q/k/v/h
    const long long SSs = (long long)SS * SS;      // per-head stride in scores

    embed_kernel<<<(BB*SS*DD + 255)/256, 256>>>(x, tok, pos, h);

    for (int l = 0; l < NLAYER; l++) {
        norm_kernel<<<M, 256>>>(h, n1s + l*DD, n1b + l*DD, hn);

        // fused QKV: one launch, grid.z in {0,1,2} selects (wq->gq, wk->gk, wv->gv)
        launch_gemm_full(hn,
                         wq + (long long)l*DD*DD, wk + (long long)l*DD*DD, wv + (long long)l*DD*DD,
                         gq, gk, gv, 0, 0,
                         M, DD, DD, DD, DD, DD, 0, 3, 0, 3, 1, 0,0,0,0,0,0);

        // scores[b,h,q,k] = Q . K  (batched over b*H, transB)
        launch_gemm(gq, gk, 0, 0, sc, SS, SS, HDIM, DD, DD, SS, 0, BB*HH, 1, HH,
                    SD, HDIM, SD, HDIM, (long long)HH*SSs, SSs);

        softmax_kernel<<<BB*HH*SS, 128>>>(sc);

        // ctx[b,q,h,:] = P @ V  (batched over b*H)
        launch_gemm(sc, gv, 0, 0, ctx, SS, HDIM, SS, SS, DD, DD, 0, BB*HH, 0, HH,
                    (long long)HH*SSs, SSs, SD, HDIM, SD, HDIM);

        // x = res + ctx @ wo + bo
        launch_gemm(ctx, wo + (long long)l*DD*DD, bo + l*DD, h, h, M, DD, DD, DD, DD, DD, 0, 1, 0, 1, 0,0,0,0,0,0);

        norm_kernel<<<M, 256>>>(h, n2s + l*DD, n2b + l*DD, hn);

        // ffn = gelu(hn @ w1 + b1)
        launch_gemm(hn, w1 + (long long)l*DD*DFF, b1 + l*DFF, 0, ffn, M, DFF, DD, DD, DFF, DFF, 1, 1, 0, 1, 0,0,0,0,0,0);
        // x = res + ffn @ w2 + b2
        launch_gemm(ffn, w2 + (long long)l*DFF*DD, b2 + l*DD, h, h, M, DD, DFF, DFF, DD, DD, 0, 1, 0, 1, 0,0,0,0,0,0);
    }

    norm_kernel<<<M, 256>>>(h, fs, fb, hn);
    // logits = hn @ head_w + head_b
    launch_gemm(hn, hw, hb, 0, out, M, VV, DD, DD, VV, VV, 0, 1, 0, 1, 0,0,0,0,0,0);
}

// round 5
// speedup vs baseline: 1.6974x; 1.2985x over previous
#include <cuda_runtime.h>
#include <math.h>
#include <stdint.h>

#define BB 2
#define SS 512
#define DD 768
#define HH 12
#define NLAYER 6
#define VV 32000
#define HDIM 64
#define DFF 3072
#define EPSF 1e-6f

// ---------------- scratch (device globals; no allocs allowed) ----------------
__device__ float g_h  [BB*SS*DD];
__device__ float g_hn [BB*SS*DD];
__device__ float g_q  [BB*SS*DD];
__device__ float g_k  [BB*SS*DD];
__device__ float g_v  [BB*SS*DD];
__device__ float g_ctx[BB*SS*DD];
__device__ float g_ffn[BB*SS*DFF];
__device__ float g_sc [BB*HH*SS*SS];
// transposed weights ([N,K] K-major)
__device__ float g_wqT[NLAYER*DD*DD];
__device__ float g_wkT[NLAYER*DD*DD];
__device__ float g_wvT[NLAYER*DD*DD];
__device__ float g_woT[NLAYER*DD*DD];
__device__ float g_w1T[NLAYER*DD*DFF];
__device__ float g_w2T[NLAYER*DFF*DD];
__device__ float g_hwT[(long long)VV*DD];

__device__ __forceinline__ uint32_t f2tf32(float x) {
    uint32_t r;
    asm("cvt.rna.tf32.f32 %0, %1;" : "=r"(r) : "f"(x));
    return r;
}

__device__ __forceinline__ float gelu_f(float v) {
    float t = v + 0.044715f * v * v * v;
    return 0.5f * v * (1.0f + tanhf(0.7978845608028654f * t));
}

// ---------------- embedding ----------------
__global__ void embed_kernel(const int* __restrict__ x, const float* __restrict__ tok,
                             const float* __restrict__ pos, float* __restrict__ out) {
    int idx = blockIdx.x * blockDim.x + threadIdx.x;
    if (idx >= BB*SS*DD) return;
    int d  = idx % DD;
    int bs = idx / DD;
    int s  = bs % SS;
    out[idx] = tok[(long long)x[bs]*DD + d] + pos[s*DD + d];
}

// ---------------- transpose: in[R][C] -> out[C][R], batched over z ----------------
__global__ void transpose_kernel(const float* __restrict__ in, float* __restrict__ out,
                                 int R, int C) {
    __shared__ float t[32][33];
    long long zoff = (long long)blockIdx.z * R * C;
    int c0 = blockIdx.x * 32, r0 = blockIdx.y * 32;
    int tx = threadIdx.x, ty = threadIdx.y;   // 32 x 8
    #pragma unroll
    for (int i = 0; i < 32; i += 8)
        t[ty + i][tx] = in[zoff + (long long)(r0 + ty + i) * C + c0 + tx];
    __syncthreads();
    #pragma unroll
    for (int i = 0; i < 32; i += 8)
        out[zoff + (long long)(c0 + ty + i) * R + r0 + tx] = t[tx][ty + i];
}

// ---------------- "DummyNorm": s*(x-mean)/(std_ddof1 + eps) + b ----------------
__global__ void norm_kernel(const float* __restrict__ x, const float* __restrict__ sc,
                            const float* __restrict__ bi, float* __restrict__ y) {
    int row = blockIdx.x;
    const float* xr = x + (long long)row * DD;
    float* yr = y + (long long)row * DD;
    int tid = threadIdx.x;
    float sum = 0.f, sq = 0.f;
    for (int i = tid; i < DD; i += 256) { float v = xr[i]; sum += v; sq += v*v; }
    __shared__ float s1[256], s2[256];
    s1[tid] = sum; s2[tid] = sq; __syncthreads();
    for (int st = 128; st > 0; st >>= 1) {
        if (tid < st) { s1[tid] += s1[tid+st]; s2[tid] += s2[tid+st]; }
        __syncthreads();
    }
    float mean = s1[0] / (float)DD;
    float var  = (s2[0] - (float)DD * mean * mean) / (float)(DD - 1);
    float inv  = 1.f / (sqrtf(fmaxf(var, 0.f)) + EPSF);
    for (int i = tid; i < DD; i += 256) yr[i] = sc[i] * (xr[i] - mean) * inv + bi[i];
}

// ---------------- masked+scaled softmax (valid keys are k >= q) ----------------
__global__ void softmax_kernel(float* __restrict__ scores) {
    int row = blockIdx.x;
    int q = row % SS;
    float* p = scores + (long long)row * SS;
    int tid = threadIdx.x;
    const float scale = 0.125f;
    float m = -1e30f;
    for (int k = q + tid; k < SS; k += 128) m = fmaxf(m, p[k] * scale);
    __shared__ float sh[128];
    sh[tid] = m; __syncthreads();
    for (int st = 64; st > 0; st >>= 1) { if (tid < st) sh[tid] = fmaxf(sh[tid], sh[tid+st]); __syncthreads(); }
    m = sh[0]; __syncthreads();
    float sum = 0.f;
    for (int k = q + tid; k < SS; k += 128) { float e = __expf(p[k]*scale - m); p[k] = e; sum += e; }
    sh[tid] = sum; __syncthreads();
    for (int st = 64; st > 0; st >>= 1) { if (tid < st) sh[tid] += sh[tid+st]; __syncthreads(); }
    float inv = 1.f / sh[0];
    for (int k = q + tid; k < SS; k += 128) p[k] *= inv;
    for (int k = tid; k < q; k += 128) p[k] = 0.f;
}

// ---------------- tf32 mma.sync GEMM: 128x128 CTA tile, 8 warps, K-chunk 32 ----------------
// C[m,n] = sum_k A[m,k] * BT[n,k]; BT is [N,K] K-major. bias/GELU/residual fused.
// blockIdx.z selects (B0,C0)/(B1,C1)/(B2,C2).
#define ROWW 36                // smem row stride in words (conflict-free fragment loads)
#define TILE_F (128*ROWW)      // floats per tile buffer
#define MMA_SMEM (4*TILE_F*4)  // 2 bufs x (A+B) = 73728 bytes

__global__ void __launch_bounds__(256)
mma_gemm(const float* __restrict__ A,
         const float* B0, const float* B1, const float* B2,
         float* C0, float* C1, float* C2,
         const float* __restrict__ bias, const float* __restrict__ res,
         int K, int ldc, int act)
{
    extern __shared__ uint32_t smem[];
    uint32_t* bufA[2] = { smem,            smem + TILE_F };
    uint32_t* bufB[2] = { smem + 2*TILE_F, smem + 3*TILE_F };

    int tid  = threadIdx.x;
    int wid  = tid >> 5;
    int lane = tid & 31;
    int warp_m = wid >> 2;          // 0..1 -> 64 rows each
    int warp_n = wid & 3;           // 0..3 -> 32 cols each
    int grp = lane >> 2, qid = lane & 3;

    int z = blockIdx.z;
    const float* Bp = (z == 0) ? B0 : ((z == 1) ? B1 : B2);
    float*       Cp = (z == 0) ? C0 : ((z == 1) ? C1 : C2);

    long long m0 = (long long)blockIdx.y * 128;
    long long n0 = (long long)blockIdx.x * 128;

    // staging indices: 128 rows x 32 k = 1024 float4 -> 4 per thread
    int s_r[4], s_c[4];
    #pragma unroll
    for (int i = 0; i < 4; i++) {
        int idx = tid + i * 256;
        s_r[i] = idx >> 3;
        s_c[i] = (idx & 7) * 4;
    }

    float acc[16][4];
    #pragma unroll
    for (int t = 0; t < 16; t++)
        #pragma unroll
        for (int u = 0; u < 4; u++) acc[t][u] = 0.f;

    // ---- prologue: stage chunk 0 into buf 0 ----
    #pragma unroll
    for (int i = 0; i < 4; i++) {
        float4 va = *(const float4*)(A  + (m0 + s_r[i]) * K + s_c[i]);
        float4 vb = *(const float4*)(Bp + (n0 + s_r[i]) * K + s_c[i]);
        uint32_t* da = bufA[0] + s_r[i]*ROWW + s_c[i];
        uint32_t* db = bufB[0] + s_r[i]*ROWW + s_c[i];
        da[0]=f2tf32(va.x); da[1]=f2tf32(va.y); da[2]=f2tf32(va.z); da[3]=f2tf32(va.w);
        db[0]=f2tf32(vb.x); db[1]=f2tf32(vb.y); db[2]=f2tf32(vb.z); db[3]=f2tf32(vb.w);
    }
    __syncthreads();

    int NC = K >> 5;
    for (int c = 0; c < NC; c++) {
        int buf = c & 1;
        float4 pa[4], pb[4];
        bool has_next = (c + 1) < NC;
        if (has_next) {
            int kt = (c + 1) * 32;
            #pragma unroll
            for (int i = 0; i < 4; i++) {
                pa[i] = *(const float4*)(A  + (m0 + s_r[i]) * K + kt + s_c[i]);
                pb[i] = *(const float4*)(Bp + (n0 + s_r[i]) * K + kt + s_c[i]);
            }
        }
        const uint32_t* As_ = bufA[buf];
        const uint32_t* Bs_ = bufB[buf];
        #pragma unroll
        for (int ks = 0; ks < 32; ks += 8) {
            uint32_t af[4][4], bf[4][2];
            #pragma unroll
            for (int i = 0; i < 4; i++) {
                int mr = warp_m*64 + i*16 + grp;
                af[i][0] = As_[(mr    )*ROWW + ks + qid];
                af[i][1] = As_[(mr + 8)*ROWW + ks + qid];
                af[i][2] = As_[(mr    )*ROWW + ks + qid + 4];
                af[i][3] = As_[(mr + 8)*ROWW + ks + qid + 4];
            }
            #pragma unroll
            for (int j = 0; j < 4; j++) {
                int nr = warp_n*32 + j*8 + grp;
                bf[j][0] = Bs_[nr*ROWW + ks + qid];
                bf[j][1] = Bs_[nr*ROWW + ks + qid + 4];
            }
            #pragma unroll
            for (int i = 0; i < 4; i++)
                #pragma unroll
                for (int j = 0; j < 4; j++) {
                    int t = i*4 + j;
                    asm volatile(
                        "mma.sync.aligned.m16n8k8.row.col.f32.tf32.tf32.f32 "
                        "{%0,%1,%2,%3}, {%4,%5,%6,%7}, {%8,%9}, {%0,%1,%2,%3};"
                        : "+f"(acc[t][0]), "+f"(acc[t][1]), "+f"(acc[t][2]), "+f"(acc[t][3])
                        : "r"(af[i][0]), "r"(af[i][1]), "r"(af[i][2]), "r"(af[i][3]),
                          "r"(bf[j][0]), "r"(bf[j][1]));
                }
        }
        if (has_next) {
            int nb = buf ^ 1;
            __syncthreads();   // everyone done reading nb's previous contents
            #pragma unroll
            for (int i = 0; i < 4; i++) {
                uint32_t* da = bufA[nb] + s_r[i]*ROWW + s_c[i];
                uint32_t* db = bufB[nb] + s_r[i]*ROWW + s_c[i];
                da[0]=f2tf32(pa[i].x); da[1]=f2tf32(pa[i].y); da[2]=f2tf32(pa[i].z); da[3]=f2tf32(pa[i].w);
                db[0]=f2tf32(pb[i].x); db[1]=f2tf32(pb[i].y); db[2]=f2tf32(pb[i].z); db[3]=f2tf32(pb[i].w);
            }
            __syncthreads();
        }
    }

    // ---- epilogue: fused bias / GELU / residual, float2 stores ----
    #pragma unroll
    for (int i = 0; i < 4; i++) {
        #pragma unroll
        for (int j = 0; j < 4; j++) {
            int t = i*4 + j;
            long long m = m0 + warp_m*64 + i*16 + grp;
            long long n = n0 + warp_n*32 + j*8 + qid*2;
            float bx = 0.f, by = 0.f;
            if (bias) { bx = bias[n]; by = bias[n+1]; }
            #pragma unroll
            for (int half = 0; half < 2; half++) {
                long long mm = m + half*8;
                float v0 = acc[t][half*2 + 0] + bx;
                float v1 = acc[t][half*2 + 1] + by;
                if (act == 1) { v0 = gelu_f(v0); v1 = gelu_f(v1); }
                if (res) {
                    float2 r2 = *(const float2*)(res + mm*ldc + n);
                    v0 += r2.x; v1 += r2.y;
                }
                float2 o; o.x = v0; o.y = v1;
                *(float2*)(Cp + mm*ldc + n) = o;
            }
        }
    }
}

// ---------------- SIMT SGEMM (attention): 64x64 tile, 128 threads, double-buffered ----------------
template<int TRANSB>
__global__ void __launch_bounds__(128)
gemm_kernel(const float* __restrict__ A, const float* __restrict__ Bm,
            float* __restrict__ C,
            int K, int lda, int ldb, int ldc, int zdiv,
            long long sa1, long long sa2, long long sb1, long long sb2,
            long long sc1, long long sc2)
{
    __shared__ float As[2][16][68];
    __shared__ float Bs[2][16][68];

    int z = blockIdx.z;
    int zd = z / zdiv, zm = z % zdiv;
    const float* Ab = A  + zd*sa1 + zm*sa2;
    const float* Bb = Bm + zd*sb1 + zm*sb2;
    float*       Cb = C  + zd*sc1 + zm*sc2;

    int tid = threadIdx.x;
    int m0 = blockIdx.y * 64;
    int n0 = blockIdx.x * 64;

    int a_r0 = tid >> 2;
    int a_kg = (tid & 3) * 4;
    int b_k0 = tid >> 4;
    int b_n4 = (tid & 15) * 4;
    int tx = tid & 15;
    int ty = tid >> 4;

    float acc[8][4];
    #pragma unroll
    for (int i = 0; i < 8; i++)
        #pragma unroll
        for (int j = 0; j < 4; j++) acc[i][j] = 0.f;

    float4 ra0, ra1, rb0, rb1;

    ra0 = *(const float4*)(Ab + (long long)(m0 + a_r0     )*lda + a_kg);
    ra1 = *(const float4*)(Ab + (long long)(m0 + a_r0 + 32)*lda + a_kg);
    if (TRANSB) {
        rb0 = *(const float4*)(Bb + (long long)(n0 + a_r0     )*ldb + a_kg);
        rb1 = *(const float4*)(Bb + (long long)(n0 + a_r0 + 32)*ldb + a_kg);
    } else {
        rb0 = *(const float4*)(Bb + (long long)(b_k0    )*ldb + n0 + b_n4);
        rb1 = *(const float4*)(Bb + (long long)(b_k0 + 8)*ldb + n0 + b_n4);
    }
    {
        As[0][a_kg+0][a_r0] = ra0.x; As[0][a_kg+1][a_r0] = ra0.y;
        As[0][a_kg+2][a_r0] = ra0.z; As[0][a_kg+3][a_r0] = ra0.w;
        As[0][a_kg+0][a_r0+32] = ra1.x; As[0][a_kg+1][a_r0+32] = ra1.y;
        As[0][a_kg+2][a_r0+32] = ra1.z; As[0][a_kg+3][a_r0+32] = ra1.w;
        if (TRANSB) {
            Bs[0][a_kg+0][a_r0] = rb0.x; Bs[0][a_kg+1][a_r0] = rb0.y;
            Bs[0][a_kg+2][a_r0] = rb0.z; Bs[0][a_kg+3][a_r0] = rb0.w;
            Bs[0][a_kg+0][a_r0+32] = rb1.x; Bs[0][a_kg+1][a_r0+32] = rb1.y;
            Bs[0][a_kg+2][a_r0+32] = rb1.z; Bs[0][a_kg+3][a_r0+32] = rb1.w;
        } else {
            *(float4*)&Bs[0][b_k0  ][b_n4] = rb0;
            *(float4*)&Bs[0][b_k0+8][b_n4] = rb1;
        }
    }
    __syncthreads();

    int buf = 0;
    for (int kt = 0; kt < K; kt += 16) {
        bool has_next = (kt + 16) < K;
        if (has_next) {
            int kn = kt + 16;
            ra0 = *(const float4*)(Ab + (long long)(m0 + a_r0     )*lda + kn + a_kg);
            ra1 = *(const float4*)(Ab + (long long)(m0 + a_r0 + 32)*lda + kn + a_kg);
            if (TRANSB) {
                rb0 = *(const float4*)(Bb + (long long)(n0 + a_r0     )*ldb + kn + a_kg);
                rb1 = *(const float4*)(Bb + (long long)(n0 + a_r0 + 32)*ldb + kn + a_kg);
            } else {
                rb0 = *(const float4*)(Bb + (long long)(kn + b_k0    )*ldb + n0 + b_n4);
                rb1 = *(const float4*)(Bb + (long long)(kn + b_k0 + 8)*ldb + n0 + b_n4);
            }
        }
        #pragma unroll
        for (int k = 0; k < 16; k++) {
            float4 x0 = *(const float4*)&As[buf][k][ty*8];
            float4 x1 = *(const float4*)&As[buf][k][ty*8 + 4];
            float4 y  = *(const float4*)&Bs[buf][k][tx*4];
            float am[8] = {x0.x, x0.y, x0.z, x0.w, x1.x, x1.y, x1.z, x1.w};
            #pragma unroll
            for (int i = 0; i < 8; i++) {
                acc[i][0] += am[i]*y.x; acc[i][1] += am[i]*y.y;
                acc[i][2] += am[i]*y.z; acc[i][3] += am[i]*y.w;
            }
        }
        if (has_next) {
            int nb = buf ^ 1;
            As[nb][a_kg+0][a_r0] = ra0.x; As[nb][a_kg+1][a_r0] = ra0.y;
            As[nb][a_kg+2][a_r0] = ra0.z; As[nb][a_kg+3][a_r0] = ra0.w;
            As[nb][a_kg+0][a_r0+32] = ra1.x; As[nb][a_kg+1][a_r0+32] = ra1.y;
            As[nb][a_kg+2][a_r0+32] = ra1.z; As[nb][a_kg+3][a_r0+32] = ra1.w;
            if (TRANSB) {
                Bs[nb][a_kg+0][a_r0] = rb0.x; Bs[nb][a_kg+1][a_r0] = rb0.y;
                Bs[nb][a_kg+2][a_r0] = rb0.z; Bs[nb][a_kg+3][a_r0] = rb0.w;
                Bs[nb][a_kg+0][a_r0+32] = rb1.x; Bs[nb][a_kg+1][a_r0+32] = rb1.y;
                Bs[nb][a_kg+2][a_r0+32] = rb1.z; Bs[nb][a_kg+3][a_r0+32] = rb1.w;
            } else {
                *(float4*)&Bs[nb][b_k0  ][b_n4] = rb0;
                *(float4*)&Bs[nb][b_k0+8][b_n4] = rb1;
            }
            __syncthreads();
            buf = nb;
        }
    }

    int n = n0 + tx*4;
    #pragma unroll
    for (int i = 0; i < 8; i++) {
        int m = m0 + ty*8 + i;
        float4 v = {acc[i][0], acc[i][1], acc[i][2], acc[i][3]};
        *(float4*)(Cb + (long long)m*ldc + n) = v;
    }
}

static void launch_gemm(const float* A, const float* Bm, float* C,
                        int M, int N, int K, int lda, int ldb, int ldc,
                        int batch, int transB, int zdiv,
                        long long sa1, long long sa2, long long sb1, long long sb2,
                        long long sc1, long long sc2)
{
    dim3 grid(N/64, M/64, batch), blk(128);
    if (transB)
        gemm_kernel<1><<<grid, blk>>>(A, Bm, C, K, lda, ldb, ldc, zdiv,
                                      sa1, sa2, sb1, sb2, sc1, sc2);
    else
        gemm_kernel<0><<<grid, blk>>>(A, Bm, C, K, lda, ldb, ldc, zdiv,
                                      sa1, sa2, sb1, sb2, sc1, sc2);
}

static void launch_mma(const float* A, const float* B0, const float* B1, const float* B2,
                       float* C0, float* C1, float* C2,
                       const float* bias, const float* res,
                       int Mtiles, int Ntiles, int K, int ldc, int act, int nsel)
{
    dim3 grid(Ntiles, Mtiles, nsel), blk(256);
    mma_gemm<<<grid, blk, MMA_SMEM>>>(A, B0, B1, B2, C0, C1, C2, bias, res, K, ldc, act);
}

extern "C" void kernel_launch(void* const* d_in, const int* in_sizes, int n_in,
                              void* d_out, int out_size)
{
    const int*   x   = (const int*)  d_in[0];
    const float* tok = (const float*)d_in[1];
    const float* pos = (const float*)d_in[2];
    const float* n1s = (const float*)d_in[3];
    const float* n1b = (const float*)d_in[4];
    const float* n2s = (const float*)d_in[5];
    const float* n2b = (const float*)d_in[6];
    const float* wq  = (const float*)d_in[7];
    const float* wk  = (const float*)d_in[8];
    const float* wv  = (const float*)d_in[9];
    const float* wo  = (const float*)d_in[10];
    const float* bo  = (const float*)d_in[11];
    const float* w1  = (const float*)d_in[12];
    const float* b1  = (const float*)d_in[13];
    const float* w2  = (const float*)d_in[14];
    const float* b2  = (const float*)d_in[15];
    const float* fs  = (const float*)d_in[16];
    const float* fb  = (const float*)d_in[17];
    const float* hw  = (const float*)d_in[18];
    const float* hb  = (const float*)d_in[19];
    float* out = (float*)d_out;

    cudaFuncSetAttribute(mma_gemm, cudaFuncAttributeMaxDynamicSharedMemorySize, MMA_SMEM);

    float *h, *hn, *gq, *gk, *gv, *ctx, *ffn, *sc;
    float *wqT, *wkT, *wvT, *woT, *w1T, *w2T, *hwT;
    cudaGetSymbolAddress((void**)&h,   g_h);
    cudaGetSymbolAddress((void**)&hn,  g_hn);
    cudaGetSymbolAddress((void**)&gq,  g_q);
    cudaGetSymbolAddress((void**)&gk,  g_k);
    cudaGetSymbolAddress((void**)&gv,  g_v);
    cudaGetSymbolAddress((void**)&ctx, g_ctx);
    cudaGetSymbolAddress((void**)&ffn, g_ffn);
    cudaGetSymbolAddress((void**)&sc,  g_sc);
    cudaGetSymbolAddress((void**)&wqT, g_wqT);
    cudaGetSymbolAddress((void**)&wkT, g_wkT);
    cudaGetSymbolAddress((void**)&wvT, g_wvT);
    cudaGetSymbolAddress((void**)&woT, g_woT);
    cudaGetSymbolAddress((void**)&w1T, g_w1T);
    cudaGetSymbolAddress((void**)&w2T, g_w2T);
    cudaGetSymbolAddress((void**)&hwT, g_hwT);

    const int M = BB * SS;                         // 1024
    const long long SD  = (long long)SS * DD;
    const long long SSs = (long long)SS * SS;

    // ---- transpose all weights to [N,K] K-major ----
    dim3 tb(32, 8);
    transpose_kernel<<<dim3(DD/32, DD/32, NLAYER), tb>>>(wq, wqT, DD, DD);
    transpose_kernel<<<dim3(DD/32, DD/32, NLAYER), tb>>>(wk, wkT, DD, DD);
    transpose_kernel<<<dim3(DD/32, DD/32, NLAYER), tb>>>(wv, wvT, DD, DD);
    transpose_kernel<<<dim3(DD/32, DD/32, NLAYER), tb>>>(wo, woT, DD, DD);
    transpose_kernel<<<dim3(DFF/32, DD/32, NLAYER), tb>>>(w1, w1T, DD, DFF);
    transpose_kernel<<<dim3(DD/32, DFF/32, NLAYER), tb>>>(w2, w2T, DFF, DD);
    transpose_kernel<<<dim3(VV/32, DD/32, 1), tb>>>(hw, hwT, DD, VV);

    embed_kernel<<<(BB*SS*DD + 255)/256, 256>>>(x, tok, pos, h);

    for (int l = 0; l < NLAYER; l++) {
        norm_kernel<<<M, 256>>>(h, n1s + l*DD, n1b + l*DD, hn);

        // fused QKV (tensor): z selects wqT->gq / wkT->gk / wvT->gv
        launch_mma(hn,
                   wqT + (long long)l*DD*DD, wkT + (long long)l*DD*DD, wvT + (long long)l*DD*DD,
                   gq, gk, gv, 0, 0, M/128, DD/128, DD, DD, 0, 3);

        // scores = Q . K^T (SIMT, batched over b*H)
        launch_gemm(gq, gk, sc, SS, SS, HDIM, DD, DD, SS, BB*HH, 1, HH,
                    SD, HDIM, SD, HDIM, (long long)HH*SSs, SSs);

        softmax_kernel<<<BB*HH*SS, 128>>>(sc);

        // ctx = P @ V (SIMT)
        launch_gemm(sc, gv, ctx, SS, HDIM, SS, SS, DD, DD, BB*HH, 0, HH,
                    (long long)HH*SSs, SSs, SD, HDIM, SD, HDIM);

        // x = res + ctx @ wo + bo (tensor)
        launch_mma(ctx, woT + (long long)l*DD*DD, 0, 0, h, 0, 0,
                   bo + l*DD, h, M/128, DD/128, DD, DD, 0, 1);

        norm_kernel<<<M, 256>>>(h, n2s + l*DD, n2b + l*DD, hn);

        // ffn = gelu(hn @ w1 + b1) (tensor)
        launch_mma(hn, w1T + (long long)l*DD*DFF, 0, 0, ffn, 0, 0,
                   b1 + l*DFF, 0, M/128, DFF/128, DD, DFF, 1, 1);
        // x = res + ffn @ w2 + b2 (tensor)
        launch_mma(ffn, w2T + (long long)l*DFF*DD, 0, 0, h, 0, 0,
                   b2 + l*DD, h, M/128, DD/128, DFF, DD, 0, 1);
    }

    norm_kernel<<<M, 256>>>(h, fs, fb, hn);
    // logits = hn @ head_w + head_b (tensor)
    launch_mma(hn, hwT, 0, 0, out, 0, 0, hb, 0, M/128, VV/128, DD, VV, 0, 1);
}

// round 6
// speedup vs baseline: 2.2845x; 1.3459x over previous
#include <cuda_runtime.h>
#include <math.h>
#include <stdint.h>

#define BB 2
#define SS 512
#define DD 768
#define HH 12
#define NLAYER 6
#define VV 32000
#define HDIM 64
#define DFF 3072
#define EPSF 1e-6f

// ---------------- scratch (device globals; no allocs allowed) ----------------
__device__ float g_h  [BB*SS*DD];
__device__ float g_hn [BB*SS*DD];
__device__ float g_q  [BB*SS*DD];
__device__ float g_k  [BB*SS*DD];
__device__ float g_v  [BB*SS*DD];
__device__ float g_ctx[BB*SS*DD];
__device__ float g_ffn[BB*SS*DFF];
__device__ float g_sc [BB*HH*SS*SS];
// transposed + tf32-rounded weights ([N,K] K-major)
__device__ float g_wqT[NLAYER*DD*DD];
__device__ float g_wkT[NLAYER*DD*DD];
__device__ float g_wvT[NLAYER*DD*DD];
__device__ float g_woT[NLAYER*DD*DD];
__device__ float g_w1T[NLAYER*DD*DFF];
__device__ float g_w2T[NLAYER*DFF*DD];
__device__ float g_hwT[(long long)VV*DD];

__device__ __forceinline__ uint32_t f2tf32(float x) {
    uint32_t r;
    asm("cvt.rna.tf32.f32 %0, %1;" : "=r"(r) : "f"(x));
    return r;
}
__device__ __forceinline__ float rndtf32(float x) { return __uint_as_float(f2tf32(x)); }

__device__ __forceinline__ float gelu_f(float v) {
    float t = v + 0.044715f * v * v * v;
    return 0.5f * v * (1.0f + tanhf(0.7978845608028654f * t));
}
__device__ __forceinline__ uint32_t smem_u32(const void* p) {
    uint32_t a;
    asm("{ .reg .u64 t; cvta.to.shared.u64 t, %1; cvt.u32.u64 %0, t; }" : "=r"(a) : "l"(p));
    return a;
}
#define CP_ASYNC16(dst, src) \
    asm volatile("cp.async.cg.shared.global [%0], [%1], 16;" :: "r"(dst), "l"(src))
#define CP_COMMIT() asm volatile("cp.async.commit_group;" ::: "memory")
#define CP_WAIT0() asm volatile("cp.async.wait_group 0;" ::: "memory")
#define CP_WAIT1() asm volatile("cp.async.wait_group 1;" ::: "memory")

// ---------------- embedding ----------------
__global__ void embed_kernel(const int* __restrict__ x, const float* __restrict__ tok,
                             const float* __restrict__ pos, float* __restrict__ out) {
    int idx = blockIdx.x * blockDim.x + threadIdx.x;
    if (idx >= BB*SS*DD) return;
    int d  = idx % DD;
    int bs = idx / DD;
    int s  = bs % SS;
    out[idx] = tok[(long long)x[bs]*DD + d] + pos[s*DD + d];
}

// ---------------- transpose + tf32 round: in[R][C] -> out[C][R] ----------------
__global__ void transpose_kernel(const float* __restrict__ in, float* __restrict__ out,
                                 int R, int C) {
    __shared__ float t[32][33];
    long long zoff = (long long)blockIdx.z * R * C;
    int c0 = blockIdx.x * 32, r0 = blockIdx.y * 32;
    int tx = threadIdx.x, ty = threadIdx.y;   // 32 x 8
    #pragma unroll
    for (int i = 0; i < 32; i += 8)
        t[ty + i][tx] = in[zoff + (long long)(r0 + ty + i) * C + c0 + tx];
    __syncthreads();
    #pragma unroll
    for (int i = 0; i < 32; i += 8)
        out[zoff + (long long)(c0 + ty + i) * R + r0 + tx] = rndtf32(t[tx][ty + i]);
}

// ---------------- "DummyNorm": s*(x-mean)/(std_ddof1 + eps) + b  (output tf32-rounded) ----------------
__global__ void norm_kernel(const float* __restrict__ x, const float* __restrict__ sc,
                            const float* __restrict__ bi, float* __restrict__ y) {
    int row = blockIdx.x;
    const float* xr = x + (long long)row * DD;
    float* yr = y + (long long)row * DD;
    int tid = threadIdx.x;
    float sum = 0.f, sq = 0.f;
    for (int i = tid; i < DD; i += 256) { float v = xr[i]; sum += v; sq += v*v; }
    __shared__ float s1[256], s2[256];
    s1[tid] = sum; s2[tid] = sq; __syncthreads();
    for (int st = 128; st > 0; st >>= 1) {
        if (tid < st) { s1[tid] += s1[tid+st]; s2[tid] += s2[tid+st]; }
        __syncthreads();
    }
    float mean = s1[0] / (float)DD;
    float var  = (s2[0] - (float)DD * mean * mean) / (float)(DD - 1);
    float inv  = 1.f / (sqrtf(fmaxf(var, 0.f)) + EPSF);
    for (int i = tid; i < DD; i += 256)
        yr[i] = rndtf32(sc[i] * (xr[i] - mean) * inv + bi[i]);
}

// ---------------- masked+scaled softmax (valid keys are k >= q) ----------------
__global__ void softmax_kernel(float* __restrict__ scores) {
    int row = blockIdx.x;
    int q = row % SS;
    float* p = scores + (long long)row * SS;
    int tid = threadIdx.x;
    const float scale = 0.125f;
    float m = -1e30f;
    for (int k = q + tid; k < SS; k += 128) m = fmaxf(m, p[k] * scale);
    __shared__ float sh[128];
    sh[tid] = m; __syncthreads();
    for (int st = 64; st > 0; st >>= 1) { if (tid < st) sh[tid] = fmaxf(sh[tid], sh[tid+st]); __syncthreads(); }
    m = sh[0]; __syncthreads();
    float sum = 0.f;
    for (int k = q + tid; k < SS; k += 128) { float e = __expf(p[k]*scale - m); p[k] = e; sum += e; }
    sh[tid] = sum; __syncthreads();
    for (int st = 64; st > 0; st >>= 1) { if (tid < st) sh[tid] += sh[tid+st]; __syncthreads(); }
    float inv = 1.f / sh[0];
    for (int k = q + tid; k < SS; k += 128) p[k] *= inv;
    for (int k = tid; k < q; k += 128) p[k] = 0.f;
}

// ---------------- tf32 mma.sync GEMM v2 ----------------
// CTA 128x128 tile, 128 threads (4 warps, warp tile 64x64), K-chunk 32,
// cp.async double-buffered staging (inputs are pre-rounded tf32).
// C[m,n] = sum_k A[m,k] * BT[n,k]; BT [N,K] K-major. bias/GELU/residual fused.
#define ROWW 36
#define TILE_W (128*ROWW)          // words per tile buffer
#define MMA_SMEM (4*TILE_W*4)      // 73728 bytes

__global__ void __launch_bounds__(128)
mma_gemm(const float* __restrict__ A,
         const float* B0, const float* B1, const float* B2,
         float* C0, float* C1, float* C2,
         const float* __restrict__ bias, const float* __restrict__ res,
         int K, int ldc, int act, int rndOut)
{
    extern __shared__ uint32_t smem[];
    uint32_t* SA[2] = { smem,            smem + TILE_W };
    uint32_t* SB[2] = { smem + 2*TILE_W, smem + 3*TILE_W };

    int tid  = threadIdx.x;
    int wid  = tid >> 5;
    int lane = tid & 31;
    int warp_m = wid >> 1;          // 0..1 -> 64 rows
    int warp_n = wid & 1;           // 0..1 -> 64 cols
    int grp = lane >> 2, qid = lane & 3;

    int z = blockIdx.z;
    const float* Bp = (z == 0) ? B0 : ((z == 1) ? B1 : B2);
    float*       Cp = (z == 0) ? C0 : ((z == 1) ? C1 : C2);

    long long m0 = (long long)blockIdx.y * 128;
    long long n0 = (long long)blockIdx.x * 128;

    // staging: 128 rows x 32 k = 1024 float4 per operand -> 8 per thread
    int s_r = tid >> 3;             // base row (0..15), +16 steps
    int s_c = (tid & 7) * 4;        // k offset
    uint32_t saddrA[2][8], saddrB[2][8];
    #pragma unroll
    for (int b = 0; b < 2; b++)
        #pragma unroll
        for (int i = 0; i < 8; i++) {
            int r = s_r + i * 16;
            saddrA[b][i] = smem_u32(SA[b] + r*ROWW + s_c);
            saddrB[b][i] = smem_u32(SB[b] + r*ROWW + s_c);
        }

    float acc[32][4];
    #pragma unroll
    for (int t = 0; t < 32; t++)
        #pragma unroll
        for (int u = 0; u < 4; u++) acc[t][u] = 0.f;

    int NC = K >> 5;

    // prologue: stage chunk 0 into buf 0
    #pragma unroll
    for (int i = 0; i < 8; i++) {
        int r = s_r + i * 16;
        CP_ASYNC16(saddrA[0][i], A  + (m0 + r) * K + s_c);
        CP_ASYNC16(saddrB[0][i], Bp + (n0 + r) * K + s_c);
    }
    CP_COMMIT();

    for (int c = 0; c < NC; c++) {
        int buf = c & 1;
        bool has_next = (c + 1) < NC;
        if (has_next) {
            int kt = (c + 1) * 32;
            int nb = buf ^ 1;
            #pragma unroll
            for (int i = 0; i < 8; i++) {
                int r = s_r + i * 16;
                CP_ASYNC16(saddrA[nb][i], A  + (m0 + r) * K + kt + s_c);
                CP_ASYNC16(saddrB[nb][i], Bp + (n0 + r) * K + kt + s_c);
            }
            CP_COMMIT();
            CP_WAIT1();
        } else {
            CP_WAIT0();
        }
        __syncthreads();

        const uint32_t* As_ = SA[buf];
        const uint32_t* Bs_ = SB[buf];
        #pragma unroll
        for (int ks = 0; ks < 32; ks += 8) {
            uint32_t af[4][4], bf[8][2];
            #pragma unroll
            for (int i = 0; i < 4; i++) {
                int mr = warp_m*64 + i*16 + grp;
                af[i][0] = As_[(mr    )*ROWW + ks + qid];
                af[i][1] = As_[(mr + 8)*ROWW + ks + qid];
                af[i][2] = As_[(mr    )*ROWW + ks + qid + 4];
                af[i][3] = As_[(mr + 8)*ROWW + ks + qid + 4];
            }
            #pragma unroll
            for (int j = 0; j < 8; j++) {
                int nr = warp_n*64 + j*8 + grp;
                bf[j][0] = Bs_[nr*ROWW + ks + qid];
                bf[j][1] = Bs_[nr*ROWW + ks + qid + 4];
            }
            #pragma unroll
            for (int i = 0; i < 4; i++)
                #pragma unroll
                for (int j = 0; j < 8; j++) {
                    int t = i*8 + j;
                    asm volatile(
                        "mma.sync.aligned.m16n8k8.row.col.f32.tf32.tf32.f32 "
                        "{%0,%1,%2,%3}, {%4,%5,%6,%7}, {%8,%9}, {%0,%1,%2,%3};"
                        : "+f"(acc[t][0]), "+f"(acc[t][1]), "+f"(acc[t][2]), "+f"(acc[t][3])
                        : "r"(af[i][0]), "r"(af[i][1]), "r"(af[i][2]), "r"(af[i][3]),
                          "r"(bf[j][0]), "r"(bf[j][1]));
                }
        }
        __syncthreads();
    }

    // ---- epilogue: fused bias / GELU / residual (+optional tf32 round), float2 stores ----
    #pragma unroll
    for (int i = 0; i < 4; i++) {
        #pragma unroll
        for (int j = 0; j < 8; j++) {
            int t = i*8 + j;
            long long m = m0 + warp_m*64 + i*16 + grp;
            long long n = n0 + warp_n*64 + j*8 + qid*2;
            float bx = 0.f, by = 0.f;
            if (bias) { bx = bias[n]; by = bias[n+1]; }
            #pragma unroll
            for (int half = 0; half < 2; half++) {
                long long mm = m + half*8;
                float v0 = acc[t][half*2 + 0] + bx;
                float v1 = acc[t][half*2 + 1] + by;
                if (act == 1) { v0 = gelu_f(v0); v1 = gelu_f(v1); }
                if (res) {
                    float2 r2 = *(const float2*)(res + mm*ldc + n);
                    v0 += r2.x; v1 += r2.y;
                }
                if (rndOut) { v0 = rndtf32(v0); v1 = rndtf32(v1); }
                float2 o; o.x = v0; o.y = v1;
                *(float2*)(Cp + mm*ldc + n) = o;
            }
        }
    }
}

// ---------------- SIMT SGEMM (attention): 64x64 tile, 128 threads, double-buffered ----------------
template<int TRANSB>
__global__ void __launch_bounds__(128)
gemm_kernel(const float* __restrict__ A, const float* __restrict__ Bm,
            float* __restrict__ C,
            int K, int lda, int ldb, int ldc, int zdiv, int rndOut,
            long long sa1, long long sa2, long long sb1, long long sb2,
            long long sc1, long long sc2)
{
    __shared__ float As[2][16][68];
    __shared__ float Bs[2][16][68];

    int z = blockIdx.z;
    int zd = z / zdiv, zm = z % zdiv;
    const float* Ab = A  + zd*sa1 + zm*sa2;
    const float* Bb = Bm + zd*sb1 + zm*sb2;
    float*       Cb = C  + zd*sc1 + zm*sc2;

    int tid = threadIdx.x;
    int m0 = blockIdx.y * 64;
    int n0 = blockIdx.x * 64;

    int a_r0 = tid >> 2;
    int a_kg = (tid & 3) * 4;
    int b_k0 = tid >> 4;
    int b_n4 = (tid & 15) * 4;
    int tx = tid & 15;
    int ty = tid >> 4;

    float acc[8][4];
    #pragma unroll
    for (int i = 0; i < 8; i++)
        #pragma unroll
        for (int j = 0; j < 4; j++) acc[i][j] = 0.f;

    float4 ra0, ra1, rb0, rb1;

    ra0 = *(const float4*)(Ab + (long long)(m0 + a_r0     )*lda + a_kg);
    ra1 = *(const float4*)(Ab + (long long)(m0 + a_r0 + 32)*lda + a_kg);
    if (TRANSB) {
        rb0 = *(const float4*)(Bb + (long long)(n0 + a_r0     )*ldb + a_kg);
        rb1 = *(const float4*)(Bb + (long long)(n0 + a_r0 + 32)*ldb + a_kg);
    } else {
        rb0 = *(const float4*)(Bb + (long long)(b_k0    )*ldb + n0 + b_n4);
        rb1 = *(const float4*)(Bb + (long long)(b_k0 + 8)*ldb + n0 + b_n4);
    }
    {
        As[0][a_kg+0][a_r0] = ra0.x; As[0][a_kg+1][a_r0] = ra0.y;
        As[0][a_kg+2][a_r0] = ra0.z; As[0][a_kg+3][a_r0] = ra0.w;
        As[0][a_kg+0][a_r0+32] = ra1.x; As[0][a_kg+1][a_r0+32] = ra1.y;
        As[0][a_kg+2][a_r0+32] = ra1.z; As[0][a_kg+3][a_r0+32] = ra1.w;
        if (TRANSB) {
            Bs[0][a_kg+0][a_r0] = rb0.x; Bs[0][a_kg+1][a_r0] = rb0.y;
            Bs[0][a_kg+2][a_r0] = rb0.z; Bs[0][a_kg+3][a_r0] = rb0.w;
            Bs[0][a_kg+0][a_r0+32] = rb1.x; Bs[0][a_kg+1][a_r0+32] = rb1.y;
            Bs[0][a_kg+2][a_r0+32] = rb1.z; Bs[0][a_kg+3][a_r0+32] = rb1.w;
        } else {
            *(float4*)&Bs[0][b_k0  ][b_n4] = rb0;
            *(float4*)&Bs[0][b_k0+8][b_n4] = rb1;
        }
    }
    __syncthreads();

    int buf = 0;
    for (int kt = 0; kt < K; kt += 16) {
        bool has_next = (kt + 16) < K;
        if (has_next) {
            int kn = kt + 16;
            ra0 = *(const float4*)(Ab + (long long)(m0 + a_r0     )*lda + kn + a_kg);
            ra1 = *(const float4*)(Ab + (long long)(m0 + a_r0 + 32)*lda + kn + a_kg);
            if (TRANSB) {
                rb0 = *(const float4*)(Bb + (long long)(n0 + a_r0     )*ldb + kn + a_kg);
                rb1 = *(const float4*)(Bb + (long long)(n0 + a_r0 + 32)*ldb + kn + a_kg);
            } else {
                rb0 = *(const float4*)(Bb + (long long)(kn + b_k0    )*ldb + n0 + b_n4);
                rb1 = *(const float4*)(Bb + (long long)(kn + b_k0 + 8)*ldb + n0 + b_n4);
            }
        }
        #pragma unroll
        for (int k = 0; k < 16; k++) {
            float4 x0 = *(const float4*)&As[buf][k][ty*8];
            float4 x1 = *(const float4*)&As[buf][k][ty*8 + 4];
            float4 y  = *(const float4*)&Bs[buf][k][tx*4];
            float am[8] = {x0.x, x0.y, x0.z, x0.w, x1.x, x1.y, x1.z, x1.w};
            #pragma unroll
            for (int i = 0; i < 8; i++) {
                acc[i][0] += am[i]*y.x; acc[i][1] += am[i]*y.y;
                acc[i][2] += am[i]*y.z; acc[i][3] += am[i]*y.w;
            }
        }
        if (has_next) {
            int nb = buf ^ 1;
            As[nb][a_kg+0][a_r0] = ra0.x; As[nb][a_kg+1][a_r0] = ra0.y;
            As[nb][a_kg+2][a_r0] = ra0.z; As[nb][a_kg+3][a_r0] = ra0.w;
            As[nb][a_kg+0][a_r0+32] = ra1.x; As[nb][a_kg+1][a_r0+32] = ra1.y;
            As[nb][a_kg+2][a_r0+32] = ra1.z; As[nb][a_kg+3][a_r0+32] = ra1.w;
            if (TRANSB) {
                Bs[nb][a_kg+0][a_r0] = rb0.x; Bs[nb][a_kg+1][a_r0] = rb0.y;
                Bs[nb][a_kg+2][a_r0] = rb0.z; Bs[nb][a_kg+3][a_r0] = rb0.w;
                Bs[nb][a_kg+0][a_r0+32] = rb1.x; Bs[nb][a_kg+1][a_r0+32] = rb1.y;
                Bs[nb][a_kg+2][a_r0+32] = rb1.z; Bs[nb][a_kg+3][a_r0+32] = rb1.w;
            } else {
                *(float4*)&Bs[nb][b_k0  ][b_n4] = rb0;
                *(float4*)&Bs[nb][b_k0+8][b_n4] = rb1;
            }
            __syncthreads();
            buf = nb;
        }
    }

    int n = n0 + tx*4;
    #pragma unroll
    for (int i = 0; i < 8; i++) {
        int m = m0 + ty*8 + i;
        float4 v = {acc[i][0], acc[i][1], acc[i][2], acc[i][3]};
        if (rndOut) { v.x = rndtf32(v.x); v.y = rndtf32(v.y); v.z = rndtf32(v.z); v.w = rndtf32(v.w); }
        *(float4*)(Cb + (long long)m*ldc + n) = v;
    }
}

static void launch_gemm(const float* A, const float* Bm, float* C,
                        int M, int N, int K, int lda, int ldb, int ldc,
                        int batch, int transB, int zdiv, int rndOut,
                        long long sa1, long long sa2, long long sb1, long long sb2,
                        long long sc1, long long sc2)
{
    dim3 grid(N/64, M/64, batch), blk(128);
    if (transB)
        gemm_kernel<1><<<grid, blk>>>(A, Bm, C, K, lda, ldb, ldc, zdiv, rndOut,
                                      sa1, sa2, sb1, sb2, sc1, sc2);
    else
        gemm_kernel<0><<<grid, blk>>>(A, Bm, C, K, lda, ldb, ldc, zdiv, rndOut,
                                      sa1, sa2, sb1, sb2, sc1, sc2);
}

static void launch_mma(const float* A, const float* B0, const float* B1, const float* B2,
                       float* C0, float* C1, float* C2,
                       const float* bias, const float* res,
                       int Mtiles, int Ntiles, int K, int ldc, int act, int nsel, int rndOut)
{
    dim3 grid(Ntiles, Mtiles, nsel), blk(128);
    mma_gemm<<<grid, blk, MMA_SMEM>>>(A, B0, B1, B2, C0, C1, C2, bias, res, K, ldc, act, rndOut);
}

extern "C" void kernel_launch(void* const* d_in, const int* in_sizes, int n_in,
                              void* d_out, int out_size)
{
    const int*   x   = (const int*)  d_in[0];
    const float* tok = (const float*)d_in[1];
    const float* pos = (const float*)d_in[2];
    const float* n1s = (const float*)d_in[3];
    const float* n1b = (const float*)d_in[4];
    const float* n2s = (const float*)d_in[5];
    const float* n2b = (const float*)d_in[6];
    const float* wq  = (const float*)d_in[7];
    const float* wk  = (const float*)d_in[8];
    const float* wv  = (const float*)d_in[9];
    const float* wo  = (const float*)d_in[10];
    const float* bo  = (const float*)d_in[11];
    const float* w1  = (const float*)d_in[12];
    const float* b1  = (const float*)d_in[13];
    const float* w2  = (const float*)d_in[14];
    const float* b2  = (const float*)d_in[15];
    const float* fs  = (const float*)d_in[16];
    const float* fb  = (const float*)d_in[17];
    const float* hw  = (const float*)d_in[18];
    const float* hb  = (const float*)d_in[19];
    float* out = (float*)d_out;

    cudaFuncSetAttribute(mma_gemm, cudaFuncAttributeMaxDynamicSharedMemorySize, MMA_SMEM);

    float *h, *hn, *gq, *gk, *gv, *ctx, *ffn, *sc;
    float *wqT, *wkT, *wvT, *woT, *w1T, *w2T, *hwT;
    cudaGetSymbolAddress((void**)&h,   g_h);
    cudaGetSymbolAddress((void**)&hn,  g_hn);
    cudaGetSymbolAddress((void**)&gq,  g_q);
    cudaGetSymbolAddress((void**)&gk,  g_k);
    cudaGetSymbolAddress((void**)&gv,  g_v);
    cudaGetSymbolAddress((void**)&ctx, g_ctx);
    cudaGetSymbolAddress((void**)&ffn, g_ffn);
    cudaGetSymbolAddress((void**)&sc,  g_sc);
    cudaGetSymbolAddress((void**)&wqT, g_wqT);
    cudaGetSymbolAddress((void**)&wkT, g_wkT);
    cudaGetSymbolAddress((void**)&wvT, g_wvT);
    cudaGetSymbolAddress((void**)&woT, g_woT);
    cudaGetSymbolAddress((void**)&w1T, g_w1T);
    cudaGetSymbolAddress((void**)&w2T, g_w2T);
    cudaGetSymbolAddress((void**)&hwT, g_hwT);

    const int M = BB * SS;                         // 1024
    const long long SD  = (long long)SS * DD;
    const long long SSs = (long long)SS * SS;

    dim3 tb(32, 8);
    // launches 0-2: QKV weight transposes (needed by launch 5)
    transpose_kernel<<<dim3(DD/32, DD/32, NLAYER), tb>>>(wq, wqT, DD, DD);
    transpose_kernel<<<dim3(DD/32, DD/32, NLAYER), tb>>>(wk, wkT, DD, DD);
    transpose_kernel<<<dim3(DD/32, DD/32, NLAYER), tb>>>(wv, wvT, DD, DD);
    // launch 3: embed, launch 4: norm
    embed_kernel<<<(BB*SS*DD + 255)/256, 256>>>(x, tok, pos, h);
    norm_kernel<<<M, 256>>>(h, n1s, n1b, hn);
    // launch 5: fused QKV mma (ncu -s 5 profiles this)
    launch_mma(hn, wqT, wkT, wvT, gq, gk, gv, 0, 0, M/128, DD/128, DD, DD, 0, 3, 0);
    // remaining weight transposes (stream-ordered before first use)
    transpose_kernel<<<dim3(DD/32, DD/32, NLAYER), tb>>>(wo, woT, DD, DD);
    transpose_kernel<<<dim3(DFF/32, DD/32, NLAYER), tb>>>(w1, w1T, DD, DFF);
    transpose_kernel<<<dim3(DD/32, DFF/32, NLAYER), tb>>>(w2, w2T, DFF, DD);
    transpose_kernel<<<dim3(VV/32, DD/32, 1), tb>>>(hw, hwT, DD, VV);

    for (int l = 0; l < NLAYER; l++) {
        if (l > 0) {
            norm_kernel<<<M, 256>>>(h, n1s + l*DD, n1b + l*DD, hn);
            launch_mma(hn,
                       wqT + (long long)l*DD*DD, wkT + (long long)l*DD*DD, wvT + (long long)l*DD*DD,
                       gq, gk, gv, 0, 0, M/128, DD/128, DD, DD, 0, 3, 0);
        }

        // scores = Q . K^T (SIMT fp32, batched over b*H)
        launch_gemm(gq, gk, sc, SS, SS, HDIM, DD, DD, SS, BB*HH, 1, HH, 0,
                    SD, HDIM, SD, HDIM, (long long)HH*SSs, SSs);

        softmax_kernel<<<BB*HH*SS, 128>>>(sc);

        // ctx = P @ V (SIMT fp32; output tf32-rounded — feeds O-proj mma)
        launch_gemm(sc, gv, ctx, SS, HDIM, SS, SS, DD, DD, BB*HH, 0, HH, 1,
                    (long long)HH*SSs, SSs, SD, HDIM, SD, HDIM);

        // x = res + ctx @ wo + bo (tensor)
        launch_mma(ctx, woT + (long long)l*DD*DD, 0, 0, h, 0, 0,
                   bo + l*DD, h, M/128, DD/128, DD, DD, 0, 1, 0);

        norm_kernel<<<M, 256>>>(h, n2s + l*DD, n2b + l*DD, hn);

        // ffn = gelu(hn @ w1 + b1) (tensor; output rounded — feeds FFN2 mma)
        launch_mma(hn, w1T + (long long)l*DD*DFF, 0, 0, ffn, 0, 0,
                   b1 + l*DFF, 0, M/128, DFF/128, DD, DFF, 1, 1, 1);
        // x = res + ffn @ w2 + b2 (tensor)
        launch_mma(ffn, w2T + (long long)l*DFF*DD, 0, 0, h, 0, 0,
                   b2 + l*DD, h, M/128, DD/128, DFF, DD, 0, 1, 0);
    }

    norm_kernel<<<M, 256>>>(h, fs, fb, hn);
    // logits = hn @ head_w + head_b (tensor)
    launch_mma(hn, hwT, 0, 0, out, 0, 0, hb, 0, M/128, VV/128, DD, VV, 0, 1, 0);
}

// round 7
// speedup vs baseline: 2.7475x; 1.2027x over previous
#include <cuda_runtime.h>
#include <math.h>
#include <stdint.h>

#define BB 2
#define SS 512
#define DD 768
#define HH 12
#define NLAYER 6
#define VV 32000
#define HDIM 64
#define DFF 3072
#define EPSF 1e-6f

// ---------------- scratch (device globals; no allocs allowed) ----------------
__device__ float g_h  [BB*SS*DD];
__device__ float g_hn [BB*SS*DD];
__device__ float g_q  [BB*SS*DD];
__device__ float g_k  [BB*SS*DD];
__device__ float g_v  [BB*SS*DD];
__device__ float g_ctx[BB*SS*DD];
__device__ float g_ffn[BB*SS*DFF];
__device__ float g_sc [BB*HH*SS*SS];
__device__ float g_part[4*BB*SS*DD];          // split-K partials (4 x 3.1M)
// tf32-rounded weights (ORIGINAL [K,N] layouts)
__device__ float g_wqR[NLAYER*DD*DD];
__device__ float g_wkR[NLAYER*DD*DD];
__device__ float g_wvR[NLAYER*DD*DD];
__device__ float g_woR[NLAYER*DD*DD];
__device__ float g_w1R[NLAYER*DD*DFF];
__device__ float g_w2R[NLAYER*DFF*DD];
__device__ float g_hwR[(long long)VV*DD];

__device__ __forceinline__ uint32_t f2tf32(float x) {
    uint32_t r;
    asm("cvt.rna.tf32.f32 %0, %1;" : "=r"(r) : "f"(x));
    return r;
}
__device__ __forceinline__ float rndtf32(float x) { return __uint_as_float(f2tf32(x)); }

__device__ __forceinline__ float gelu_f(float v) {
    float t = v + 0.044715f * v * v * v;
    return 0.5f * v * (1.0f + tanhf(0.7978845608028654f * t));
}
__device__ __forceinline__ uint32_t smem_u32(const void* p) {
    uint32_t a;
    asm("{ .reg .u64 t; cvta.to.shared.u64 t, %1; cvt.u32.u64 %0, t; }" : "=r"(a) : "l"(p));
    return a;
}
#define CP_ASYNC16(dst, src) \
    asm volatile("cp.async.cg.shared.global [%0], [%1], 16;" :: "r"(dst), "l"(src))
#define CP_COMMIT() asm volatile("cp.async.commit_group;" ::: "memory")
#define CP_WAIT0() asm volatile("cp.async.wait_group 0;" ::: "memory")
#define CP_WAIT1() asm volatile("cp.async.wait_group 1;" ::: "memory")

// ---------------- embedding ----------------
__global__ void embed_kernel(const int* __restrict__ x, const float* __restrict__ tok,
                             const float* __restrict__ pos, float* __restrict__ out) {
    int idx = blockIdx.x * blockDim.x + threadIdx.x;
    if (idx >= BB*SS*DD) return;
    int d  = idx % DD;
    int bs = idx / DD;
    int s  = bs % SS;
    out[idx] = tok[(long long)x[bs]*DD + d] + pos[s*DD + d];
}

// ---------------- tf32 round copy (same layout) ----------------
__global__ void round_kernel(const float* __restrict__ in, float* __restrict__ out, long long n4) {
    long long i = (long long)blockIdx.x * blockDim.x + threadIdx.x;
    if (i >= n4) return;
    float4 v = ((const float4*)in)[i];
    v.x = rndtf32(v.x); v.y = rndtf32(v.y); v.z = rndtf32(v.z); v.w = rndtf32(v.w);
    ((float4*)out)[i] = v;
}

// ---------------- split-K reduce: out = [res +] (sum partials + bias) [gelu] ----------------
__global__ void reduce4_kernel(const float* __restrict__ part, const float* __restrict__ bias,
                               const float* __restrict__ res, float* __restrict__ out,
                               int MN, int N, int act, int rndOut) {
    int i = blockIdx.x * blockDim.x + threadIdx.x;
    if (i >= MN) return;
    float v = part[i] + part[i + MN] + part[i + 2*MN] + part[i + 3*MN];
    v += bias[i % N];
    if (act) v = gelu_f(v);
    if (res) v += res[i];
    if (rndOut) v = rndtf32(v);
    out[i] = v;
}

// ---------------- "DummyNorm" (output tf32-rounded) ----------------
__global__ void norm_kernel(const float* __restrict__ x, const float* __restrict__ sc,
                            const float* __restrict__ bi, float* __restrict__ y) {
    int row = blockIdx.x;
    const float* xr = x + (long long)row * DD;
    float* yr = y + (long long)row * DD;
    int tid = threadIdx.x;
    float sum = 0.f, sq = 0.f;
    for (int i = tid; i < DD; i += 256) { float v = xr[i]; sum += v; sq += v*v; }
    __shared__ float s1[256], s2[256];
    s1[tid] = sum; s2[tid] = sq; __syncthreads();
    for (int st = 128; st > 0; st >>= 1) {
        if (tid < st) { s1[tid] += s1[tid+st]; s2[tid] += s2[tid+st]; }
        __syncthreads();
    }
    float mean = s1[0] / (float)DD;
    float var  = (s2[0] - (float)DD * mean * mean) / (float)(DD - 1);
    float inv  = 1.f / (sqrtf(fmaxf(var, 0.f)) + EPSF);
    for (int i = tid; i < DD; i += 256)
        yr[i] = rndtf32(sc[i] * (xr[i] - mean) * inv + bi[i]);
}

// ---------------- masked+scaled softmax (valid keys are k >= q) ----------------
__global__ void softmax_kernel(float* __restrict__ scores) {
    int row = blockIdx.x;
    int q = row % SS;
    float* p = scores + (long long)row * SS;
    int tid = threadIdx.x;
    const float scale = 0.125f;
    float m = -1e30f;
    for (int k = q + tid; k < SS; k += 128) m = fmaxf(m, p[k] * scale);
    __shared__ float sh[128];
    sh[tid] = m; __syncthreads();
    for (int st = 64; st > 0; st >>= 1) { if (tid < st) sh[tid] = fmaxf(sh[tid], sh[tid+st]); __syncthreads(); }
    m = sh[0]; __syncthreads();
    float sum = 0.f;
    for (int k = q + tid; k < SS; k += 128) { float e = __expf(p[k]*scale - m); p[k] = e; sum += e; }
    sh[tid] = sum; __syncthreads();
    for (int st = 64; st > 0; st >>= 1) { if (tid < st) sh[tid] += sh[tid+st]; __syncthreads(); }
    float inv = 1.f / sh[0];
    for (int k = q + tid; k < SS; k += 128) p[k] *= inv;
    for (int k = tid; k < q; k += 128) p[k] = 0.f;
}

// ---------------- tf32 mma.sync GEMM v3 ----------------
// CTA 128x128, 128 threads (4 warps, 64x64 warp tile), K-chunk 32, cp.async double-buffered.
// A [M,K] row-major (lda), B [K,N] row-major (ldb) -> row.col via smem layouts.
// Modes:
//   nsel==3 : blockIdx.z selects (B0,C0)/(B1,C1)/(B2,C2)       [fused QKV]
//   splitStride>0 : blockIdx.z = K-slice s; A,B advance s*K; C = C0 + s*splitStride,
//                   raw fp32 partial store (no bias/act/res)
#define AROW 36
#define BROW 132
#define SA_W (128*AROW)            // words per A buffer
#define SB_W (32*BROW)             // words per B buffer
#define MMA_SMEM ((2*SA_W + 2*SB_W)*4)   // 70656 bytes

__global__ void __launch_bounds__(128)
mma_gemm(const float* __restrict__ A,
         const float* B0, const float* B1, const float* B2,
         float* C0, float* C1, float* C2,
         const float* __restrict__ bias, const float* __restrict__ res,
         int K, int lda, int ldb, int ldc, int act, int nsel,
         long long splitStride, int rndOut)
{
    extern __shared__ uint32_t smem[];
    uint32_t* SA[2] = { smem,          smem + SA_W };
    uint32_t* SB[2] = { smem + 2*SA_W, smem + 2*SA_W + SB_W };

    int tid  = threadIdx.x;
    int wid  = tid >> 5;
    int lane = tid & 31;
    int warp_m = wid >> 1;
    int warp_n = wid & 1;
    int grp = lane >> 2, qid = lane & 3;

    int z = blockIdx.z;
    const float* Ap = A;
    const float* Bp = B0;
    float*       Cp = C0;
    if (nsel == 3) {
        Bp = (z == 0) ? B0 : ((z == 1) ? B1 : B2);
        Cp = (z == 0) ? C0 : ((z == 1) ? C1 : C2);
    } else if (splitStride > 0) {
        Ap = A  + (long long)z * K;          // column offset (row stride lda)
        Bp = B0 + (long long)z * K * ldb;    // row offset
        Cp = C0 + (long long)z * splitStride;
    }

    long long m0 = (long long)blockIdx.y * 128;
    long long n0 = (long long)blockIdx.x * 128;

    // A staging: 128 rows x 32k = 1024 float4 -> 8/thread
    int a_r = tid >> 3;                // 0..15, +16 steps
    int a_c = (tid & 7) * 4;           // k word offset
    // B staging: 32 rows x 128n = 1024 float4 -> 8/thread
    int b_r = tid >> 4;                // 0..7, +8 steps (4 groups of rows? -> rows b_r + i*8, i<4, 2 f4 each)
    int b_c = (tid & 15) * 8;          // n word offset (2 float4)

    float acc[32][4];
    #pragma unroll
    for (int t = 0; t < 32; t++)
        #pragma unroll
        for (int u = 0; u < 4; u++) acc[t][u] = 0.f;

    int NC = K >> 5;

    // prologue: stage chunk 0 -> buf 0
    #pragma unroll
    for (int i = 0; i < 8; i++) {
        int r = a_r + i * 16;
        CP_ASYNC16(smem_u32(SA[0] + r*AROW + a_c), Ap + (m0 + r) * lda + a_c);
    }
    #pragma unroll
    for (int i = 0; i < 4; i++) {
        int r = b_r + i * 8;
        CP_ASYNC16(smem_u32(SB[0] + r*BROW + b_c),     Bp + (long long)r * ldb + n0 + b_c);
        CP_ASYNC16(smem_u32(SB[0] + r*BROW + b_c + 4), Bp + (long long)r * ldb + n0 + b_c + 4);
    }
    CP_COMMIT();

    for (int c = 0; c < NC; c++) {
        int buf = c & 1;
        bool has_next = (c + 1) < NC;
        if (has_next) {
            int kt = (c + 1) * 32;
            int nb = buf ^ 1;
            #pragma unroll
            for (int i = 0; i < 8; i++) {
                int r = a_r + i * 16;
                CP_ASYNC16(smem_u32(SA[nb] + r*AROW + a_c), Ap + (m0 + r) * lda + kt + a_c);
            }
            #pragma unroll
            for (int i = 0; i < 4; i++) {
                int r = b_r + i * 8;
                const float* src = Bp + (long long)(kt + r) * ldb + n0 + b_c;
                CP_ASYNC16(smem_u32(SB[nb] + r*BROW + b_c),     src);
                CP_ASYNC16(smem_u32(SB[nb] + r*BROW + b_c + 4), src + 4);
            }
            CP_COMMIT();
            CP_WAIT1();
        } else {
            CP_WAIT0();
        }
        __syncthreads();

        const uint32_t* As_ = SA[buf];
        const uint32_t* Bs_ = SB[buf];
        #pragma unroll
        for (int ks = 0; ks < 32; ks += 8) {
            uint32_t af[4][4], bf[8][2];
            #pragma unroll
            for (int i = 0; i < 4; i++) {
                int mr = warp_m*64 + i*16 + grp;
                af[i][0] = As_[(mr    )*AROW + ks + qid];
                af[i][1] = As_[(mr + 8)*AROW + ks + qid];
                af[i][2] = As_[(mr    )*AROW + ks + qid + 4];
                af[i][3] = As_[(mr + 8)*AROW + ks + qid + 4];
            }
            #pragma unroll
            for (int j = 0; j < 8; j++) {
                int nr = warp_n*64 + j*8 + grp;
                bf[j][0] = Bs_[(ks + qid    )*BROW + nr];
                bf[j][1] = Bs_[(ks + qid + 4)*BROW + nr];
            }
            #pragma unroll
            for (int i = 0; i < 4; i++)
                #pragma unroll
                for (int j = 0; j < 8; j++) {
                    int t = i*8 + j;
                    asm volatile(
                        "mma.sync.aligned.m16n8k8.row.col.f32.tf32.tf32.f32 "
                        "{%0,%1,%2,%3}, {%4,%5,%6,%7}, {%8,%9}, {%0,%1,%2,%3};"
                        : "+f"(acc[t][0]), "+f"(acc[t][1]), "+f"(acc[t][2]), "+f"(acc[t][3])
                        : "r"(af[i][0]), "r"(af[i][1]), "r"(af[i][2]), "r"(af[i][3]),
                          "r"(bf[j][0]), "r"(bf[j][1]));
                }
        }
        __syncthreads();
    }

    // ---- epilogue ----
    bool raw = (splitStride > 0);
    #pragma unroll
    for (int i = 0; i < 4; i++) {
        #pragma unroll
        for (int j = 0; j < 8; j++) {
            int t = i*8 + j;
            long long m = m0 + warp_m*64 + i*16 + grp;
            long long n = n0 + warp_n*64 + j*8 + qid*2;
            float bx = 0.f, by = 0.f;
            if (!raw && bias) { bx = bias[n]; by = bias[n+1]; }
            #pragma unroll
            for (int half = 0; half < 2; half++) {
                long long mm = m + half*8;
                float v0 = acc[t][half*2 + 0] + bx;
                float v1 = acc[t][half*2 + 1] + by;
                if (!raw) {
                    if (act == 1) { v0 = gelu_f(v0); v1 = gelu_f(v1); }
                    if (res) {
                        float2 r2 = *(const float2*)(res + mm*ldc + n);
                        v0 += r2.x; v1 += r2.y;
                    }
                    if (rndOut) { v0 = rndtf32(v0); v1 = rndtf32(v1); }
                }
                float2 o; o.x = v0; o.y = v1;
                *(float2*)(Cp + mm*ldc + n) = o;
            }
        }
    }
}

// ---------------- SIMT SGEMM (attention): 64x64 tile, 128 threads, double-buffered ----------------
template<int TRANSB>
__global__ void __launch_bounds__(128)
gemm_kernel(const float* __restrict__ A, const float* __restrict__ Bm,
            float* __restrict__ C,
            int K, int lda, int ldb, int ldc, int zdiv, int rndOut,
            long long sa1, long long sa2, long long sb1, long long sb2,
            long long sc1, long long sc2)
{
    __shared__ float As[2][16][68];
    __shared__ float Bs[2][16][68];

    int z = blockIdx.z;
    int zd = z / zdiv, zm = z % zdiv;
    const float* Ab = A  + zd*sa1 + zm*sa2;
    const float* Bb = Bm + zd*sb1 + zm*sb2;
    float*       Cb = C  + zd*sc1 + zm*sc2;

    int tid = threadIdx.x;
    int m0 = blockIdx.y * 64;
    int n0 = blockIdx.x * 64;

    int a_r0 = tid >> 2;
    int a_kg = (tid & 3) * 4;
    int b_k0 = tid >> 4;
    int b_n4 = (tid & 15) * 4;
    int tx = tid & 15;
    int ty = tid >> 4;

    float acc[8][4];
    #pragma unroll
    for (int i = 0; i < 8; i++)
        #pragma unroll
        for (int j = 0; j < 4; j++) acc[i][j] = 0.f;

    float4 ra0, ra1, rb0, rb1;

    ra0 = *(const float4*)(Ab + (long long)(m0 + a_r0     )*lda + a_kg);
    ra1 = *(const float4*)(Ab + (long long)(m0 + a_r0 + 32)*lda + a_kg);
    if (TRANSB) {
        rb0 = *(const float4*)(Bb + (long long)(n0 + a_r0     )*ldb + a_kg);
        rb1 = *(const float4*)(Bb + (long long)(n0 + a_r0 + 32)*ldb + a_kg);
    } else {
        rb0 = *(const float4*)(Bb + (long long)(b_k0    )*ldb + n0 + b_n4);
        rb1 = *(const float4*)(Bb + (long long)(b_k0 + 8)*ldb + n0 + b_n4);
    }
    {
        As[0][a_kg+0][a_r0] = ra0.x; As[0][a_kg+1][a_r0] = ra0.y;
        As[0][a_kg+2][a_r0] = ra0.z; As[0][a_kg+3][a_r0] = ra0.w;
        As[0][a_kg+0][a_r0+32] = ra1.x; As[0][a_kg+1][a_r0+32] = ra1.y;
        As[0][a_kg+2][a_r0+32] = ra1.z; As[0][a_kg+3][a_r0+32] = ra1.w;
        if (TRANSB) {
            Bs[0][a_kg+0][a_r0] = rb0.x; Bs[0][a_kg+1][a_r0] = rb0.y;
            Bs[0][a_kg+2][a_r0] = rb0.z; Bs[0][a_kg+3][a_r0] = rb0.w;
            Bs[0][a_kg+0][a_r0+32] = rb1.x; Bs[0][a_kg+1][a_r0+32] = rb1.y;
            Bs[0][a_kg+2][a_r0+32] = rb1.z; Bs[0][a_kg+3][a_r0+32] = rb1.w;
        } else {
            *(float4*)&Bs[0][b_k0  ][b_n4] = rb0;
            *(float4*)&Bs[0][b_k0+8][b_n4] = rb1;
        }
    }
    __syncthreads();

    int buf = 0;
    for (int kt = 0; kt < K; kt += 16) {
        bool has_next = (kt + 16) < K;
        if (has_next) {
            int kn = kt + 16;
            ra0 = *(const float4*)(Ab + (long long)(m0 + a_r0     )*lda + kn + a_kg);
            ra1 = *(const float4*)(Ab + (long long)(m0 + a_r0 + 32)*lda + kn + a_kg);
            if (TRANSB) {
                rb0 = *(const float4*)(Bb + (long long)(n0 + a_r0     )*ldb + kn + a_kg);
                rb1 = *(const float4*)(Bb + (long long)(n0 + a_r0 + 32)*ldb + kn + a_kg);
            } else {
                rb0 = *(const float4*)(Bb + (long long)(kn + b_k0    )*ldb + n0 + b_n4);
                rb1 = *(const float4*)(Bb + (long long)(kn + b_k0 + 8)*ldb + n0 + b_n4);
            }
        }
        #pragma unroll
        for (int k = 0; k < 16; k++) {
            float4 x0 = *(const float4*)&As[buf][k][ty*8];
            float4 x1 = *(const float4*)&As[buf][k][ty*8 + 4];
            float4 y  = *(const float4*)&Bs[buf][k][tx*4];
            float am[8] = {x0.x, x0.y, x0.z, x0.w, x1.x, x1.y, x1.z, x1.w};
            #pragma unroll
            for (int i = 0; i < 8; i++) {
                acc[i][0] += am[i]*y.x; acc[i][1] += am[i]*y.y;
                acc[i][2] += am[i]*y.z; acc[i][3] += am[i]*y.w;
            }
        }
        if (has_next) {
            int nb = buf ^ 1;
            As[nb][a_kg+0][a_r0] = ra0.x; As[nb][a_kg+1][a_r0] = ra0.y;
            As[nb][a_kg+2][a_r0] = ra0.z; As[nb][a_kg+3][a_r0] = ra0.w;
            As[nb][a_kg+0][a_r0+32] = ra1.x; As[nb][a_kg+1][a_r0+32] = ra1.y;
            As[nb][a_kg+2][a_r0+32] = ra1.z; As[nb][a_kg+3][a_r0+32] = ra1.w;
            if (TRANSB) {
                Bs[nb][a_kg+0][a_r0] = rb0.x; Bs[nb][a_kg+1][a_r0] = rb0.y;
                Bs[nb][a_kg+2][a_r0] = rb0.z; Bs[nb][a_kg+3][a_r0] = rb0.w;
                Bs[nb][a_kg+0][a_r0+32] = rb1.x; Bs[nb][a_kg+1][a_r0+32] = rb1.y;
                Bs[nb][a_kg+2][a_r0+32] = rb1.z; Bs[nb][a_kg+3][a_r0+32] = rb1.w;
            } else {
                *(float4*)&Bs[nb][b_k0  ][b_n4] = rb0;
                *(float4*)&Bs[nb][b_k0+8][b_n4] = rb1;
            }
            __syncthreads();
            buf = nb;
        }
    }

    int n = n0 + tx*4;
    #pragma unroll
    for (int i = 0; i < 8; i++) {
        int m = m0 + ty*8 + i;
        float4 v = {acc[i][0], acc[i][1], acc[i][2], acc[i][3]};
        if (rndOut) { v.x = rndtf32(v.x); v.y = rndtf32(v.y); v.z = rndtf32(v.z); v.w = rndtf32(v.w); }
        *(float4*)(Cb + (long long)m*ldc + n) = v;
    }
}

static void launch_gemm(const float* A, const float* Bm, float* C,
                        int M, int N, int K, int lda, int ldb, int ldc,
                        int batch, int transB, int zdiv, int rndOut,
                        long long sa1, long long sa2, long long sb1, long long sb2,
                        long long sc1, long long sc2)
{
    dim3 grid(N/64, M/64, batch), blk(128);
    if (transB)
        gemm_kernel<1><<<grid, blk>>>(A, Bm, C, K, lda, ldb, ldc, zdiv, rndOut,
                                      sa1, sa2, sb1, sb2, sc1, sc2);
    else
        gemm_kernel<0><<<grid, blk>>>(A, Bm, C, K, lda, ldb, ldc, zdiv, rndOut,
                                      sa1, sa2, sb1, sb2, sc1, sc2);
}

// normal (non-split) mma launch; B in [K,N], ldb=N
static void launch_mma(const float* A, const float* B0, const float* B1, const float* B2,
                       float* C0, float* C1, float* C2,
                       const float* bias, const float* res,
                       int M, int N, int K, int ldb, int ldc, int act, int nsel, int rndOut)
{
    dim3 grid(N/128, M/128, nsel), blk(128);
    mma_gemm<<<grid, blk, MMA_SMEM>>>(A, B0, B1, B2, C0, C1, C2, bias, res,
                                      K, K, ldb, ldc, act, nsel, 0, rndOut);
}

// split-K x4: partial fp32 to part; then reduce fuses bias/act/res
static void launch_mma_split4(const float* A, const float* B, float* part,
                              const float* bias, const float* res, float* out,
                              int M, int N, int K, int act, int rndOut)
{
    int Ks = K / 4;
    dim3 grid(N/128, M/128, 4), blk(128);
    mma_gemm<<<grid, blk, MMA_SMEM>>>(A, B, B, B, part, part, part, 0, 0,
                                      Ks, K, N, N, 0, 1, (long long)M*N, 0);
    int MN = M * N;
    reduce4_kernel<<<(MN + 255)/256, 256>>>(part, bias, res, out, MN, N, act, rndOut);
}

extern "C" void kernel_launch(void* const* d_in, const int* in_sizes, int n_in,
                              void* d_out, int out_size)
{
    const int*   x   = (const int*)  d_in[0];
    const float* tok = (const float*)d_in[1];
    const float* pos = (const float*)d_in[2];
    const float* n1s = (const float*)d_in[3];
    const float* n1b = (const float*)d_in[4];
    const float* n2s = (const float*)d_in[5];
    const float* n2b = (const float*)d_in[6];
    const float* wq  = (const float*)d_in[7];
    const float* wk  = (const float*)d_in[8];
    const float* wv  = (const float*)d_in[9];
    const float* wo  = (const float*)d_in[10];
    const float* bo  = (const float*)d_in[11];
    const float* w1  = (const float*)d_in[12];
    const float* b1  = (const float*)d_in[13];
    const float* w2  = (const float*)d_in[14];
    const float* b2  = (const float*)d_in[15];
    const float* fs  = (const float*)d_in[16];
    const float* fb  = (const float*)d_in[17];
    const float* hw  = (const float*)d_in[18];
    const float* hb  = (const float*)d_in[19];
    float* out = (float*)d_out;

    cudaFuncSetAttribute(mma_gemm, cudaFuncAttributeMaxDynamicSharedMemorySize, MMA_SMEM);

    float *h, *hn, *gq, *gk, *gv, *ctx, *ffn, *sc, *part;
    float *wqR, *wkR, *wvR, *woR, *w1R, *w2R, *hwR;
    cudaGetSymbolAddress((void**)&h,   g_h);
    cudaGetSymbolAddress((void**)&hn,  g_hn);
    cudaGetSymbolAddress((void**)&gq,  g_q);
    cudaGetSymbolAddress((void**)&gk,  g_k);
    cudaGetSymbolAddress((void**)&gv,  g_v);
    cudaGetSymbolAddress((void**)&ctx, g_ctx);
    cudaGetSymbolAddress((void**)&ffn, g_ffn);
    cudaGetSymbolAddress((void**)&sc,  g_sc);
    cudaGetSymbolAddress((void**)&part, g_part);
    cudaGetSymbolAddress((void**)&wqR, g_wqR);
    cudaGetSymbolAddress((void**)&wkR, g_wkR);
    cudaGetSymbolAddress((void**)&wvR, g_wvR);
    cudaGetSymbolAddress((void**)&woR, g_woR);
    cudaGetSymbolAddress((void**)&w1R, g_w1R);
    cudaGetSymbolAddress((void**)&w2R, g_w2R);
    cudaGetSymbolAddress((void**)&hwR, g_hwR);

    const int M = BB * SS;                         // 1024
    const long long SD  = (long long)SS * DD;
    const long long SSs = (long long)SS * SS;

    // ---- tf32-round weights (same layout; streaming) ----
    {
        long long n4;
        n4 = (long long)NLAYER*DD*DD/4;
        round_kernel<<<(unsigned)((n4+255)/256), 256>>>(wq, wqR, n4);
        round_kernel<<<(unsigned)((n4+255)/256), 256>>>(wk, wkR, n4);
        round_kernel<<<(unsigned)((n4+255)/256), 256>>>(wv, wvR, n4);
        round_kernel<<<(unsigned)((n4+255)/256), 256>>>(wo, woR, n4);
        n4 = (long long)NLAYER*DD*DFF/4;
        round_kernel<<<(unsigned)((n4+255)/256), 256>>>(w1, w1R, n4);
        round_kernel<<<(unsigned)((n4+255)/256), 256>>>(w2, w2R, n4);
        n4 = (long long)VV*DD/4;
        round_kernel<<<(unsigned)((n4+255)/256), 256>>>(hw, hwR, n4);
    }

    embed_kernel<<<(BB*SS*DD + 255)/256, 256>>>(x, tok, pos, h);

    for (int l = 0; l < NLAYER; l++) {
        norm_kernel<<<M, 256>>>(h, n1s + l*DD, n1b + l*DD, hn);

        // fused QKV (tensor, B=[K,N])
        launch_mma(hn, wqR + (long long)l*DD*DD, wkR + (long long)l*DD*DD, wvR + (long long)l*DD*DD,
                   gq, gk, gv, 0, 0, M, DD, DD, DD, DD, 0, 3, 0);

        // scores = Q . K^T (SIMT fp32, batched over b*H)
        launch_gemm(gq, gk, sc, SS, SS, HDIM, DD, DD, SS, BB*HH, 1, HH, 0,
                    SD, HDIM, SD, HDIM, (long long)HH*SSs, SSs);

        softmax_kernel<<<BB*HH*SS, 128>>>(sc);

        // ctx = P @ V (SIMT fp32; output tf32-rounded — feeds O-proj mma)
        launch_gemm(sc, gv, ctx, SS, HDIM, SS, SS, DD, DD, BB*HH, 0, HH, 1,
                    (long long)HH*SSs, SSs, SD, HDIM, SD, HDIM);

        // x = res + ctx @ wo + bo (tensor, split-K x4 for grid fill)
        launch_mma_split4(ctx, woR + (long long)l*DD*DD, part, bo + l*DD, h, h,
                          M, DD, DD, 0, 0);

        norm_kernel<<<M, 256>>>(h, n2s + l*DD, n2b + l*DD, hn);

        // ffn = gelu(hn @ w1 + b1) (tensor; output rounded)
        launch_mma(hn, w1R + (long long)l*DD*DFF, 0, 0, ffn, 0, 0,
                   b1 + l*DFF, 0, M, DFF, DD, DFF, DFF, 1, 1, 1);

        // x = res + ffn @ w2 + b2 (tensor, split-K x4)
        launch_mma_split4(ffn, w2R + (long long)l*DFF*DD, part, b2 + l*DD, h, h,
                          M, DD, DFF, 0, 0);
    }

    norm_kernel<<<M, 256>>>(h, fs, fb, hn);
    // logits = hn @ head_w + head_b (tensor)
    launch_mma(hn, hwR, 0, 0, out, 0, 0, hb, 0, M, VV, DD, VV, VV, 0, 1, 0);
}

// round 8
// speedup vs baseline: 2.8593x; 1.0407x over previous
#include <cuda_runtime.h>
#include <math.h>
#include <stdint.h>

#define BB 2
#define SS 512
#define DD 768
#define HH 12
#define NLAYER 6
#define VV 32000
#define HDIM 64
#define DFF 3072
#define EPSF 1e-6f

// ---------------- scratch (device globals; no allocs allowed) ----------------
__device__ float g_h  [BB*SS*DD];
__device__ float g_hn [BB*SS*DD];
__device__ float g_q  [BB*SS*DD];
__device__ float g_k  [BB*SS*DD];
__device__ float g_v  [BB*SS*DD];
__device__ float g_ctx[BB*SS*DD];
__device__ float g_ffn[BB*SS*DFF];
__device__ float g_sc [BB*HH*SS*SS];
__device__ float g_part[4*BB*SS*DD];
// tf32-rounded weights (ORIGINAL [K,N] layouts)
__device__ float g_wqR[NLAYER*DD*DD];
__device__ float g_wkR[NLAYER*DD*DD];
__device__ float g_wvR[NLAYER*DD*DD];
__device__ float g_woR[NLAYER*DD*DD];
__device__ float g_w1R[NLAYER*DD*DFF];
__device__ float g_w2R[NLAYER*DFF*DD];
__device__ float g_hwR[(long long)VV*DD];

__device__ __forceinline__ uint32_t f2tf32(float x) {
    uint32_t r;
    asm("cvt.rna.tf32.f32 %0, %1;" : "=r"(r) : "f"(x));
    return r;
}
__device__ __forceinline__ float rndtf32(float x) { return __uint_as_float(f2tf32(x)); }

__device__ __forceinline__ float gelu_f(float v) {
    float t = v + 0.044715f * v * v * v;
    return 0.5f * v * (1.0f + tanhf(0.7978845608028654f * t));
}
__device__ __forceinline__ uint32_t smem_u32(const void* p) {
    uint32_t a;
    asm("{ .reg .u64 t; cvta.to.shared.u64 t, %1; cvt.u32.u64 %0, t; }" : "=r"(a) : "l"(p));
    return a;
}
#define CP_ASYNC16(dst, src) \
    asm volatile("cp.async.cg.shared.global [%0], [%1], 16;" :: "r"(dst), "l"(src))
#define CP_COMMIT() asm volatile("cp.async.commit_group;" ::: "memory")
#define CP_WAIT0() asm volatile("cp.async.wait_group 0;" ::: "memory")
#define CP_WAIT1() asm volatile("cp.async.wait_group 1;" ::: "memory")

// ---------------- embedding ----------------
__global__ void embed_kernel(const int* __restrict__ x, const float* __restrict__ tok,
                             const float* __restrict__ pos, float* __restrict__ out) {
    int idx = blockIdx.x * blockDim.x + threadIdx.x;
    if (idx >= BB*SS*DD) return;
    int d  = idx % DD;
    int bs = idx / DD;
    int s  = bs % SS;
    out[idx] = tok[(long long)x[bs]*DD + d] + pos[s*DD + d];
}

// ---------------- tf32 round copy ----------------
__global__ void round_kernel(const float* __restrict__ in, float* __restrict__ out, long long n4) {
    long long i = (long long)blockIdx.x * blockDim.x + threadIdx.x;
    if (i >= n4) return;
    float4 v = ((const float4*)in)[i];
    v.x = rndtf32(v.x); v.y = rndtf32(v.y); v.z = rndtf32(v.z); v.w = rndtf32(v.w);
    ((float4*)out)[i] = v;
}

// ---------------- split-K reduce ----------------
__global__ void reduce4_kernel(const float* __restrict__ part, const float* __restrict__ bias,
                               const float* __restrict__ res, float* __restrict__ out,
                               int MN, int N, int act, int rndOut) {
    int i = blockIdx.x * blockDim.x + threadIdx.x;
    if (i >= MN) return;
    float v = part[i] + part[i + MN] + part[i + 2*MN] + part[i + 3*MN];
    v += bias[i % N];
    if (act) v = gelu_f(v);
    if (res) v += res[i];
    if (rndOut) v = rndtf32(v);
    out[i] = v;
}

// ---------------- "DummyNorm" (output tf32-rounded) ----------------
__global__ void norm_kernel(const float* __restrict__ x, const float* __restrict__ sc,
                            const float* __restrict__ bi, float* __restrict__ y) {
    int row = blockIdx.x;
    const float* xr = x + (long long)row * DD;
    float* yr = y + (long long)row * DD;
    int tid = threadIdx.x;
    float sum = 0.f, sq = 0.f;
    for (int i = tid; i < DD; i += 256) { float v = xr[i]; sum += v; sq += v*v; }
    __shared__ float s1[256], s2[256];
    s1[tid] = sum; s2[tid] = sq; __syncthreads();
    for (int st = 128; st > 0; st >>= 1) {
        if (tid < st) { s1[tid] += s1[tid+st]; s2[tid] += s2[tid+st]; }
        __syncthreads();
    }
    float mean = s1[0] / (float)DD;
    float var  = (s2[0] - (float)DD * mean * mean) / (float)(DD - 1);
    float inv  = 1.f / (sqrtf(fmaxf(var, 0.f)) + EPSF);
    for (int i = tid; i < DD; i += 256)
        yr[i] = rndtf32(sc[i] * (xr[i] - mean) * inv + bi[i]);
}

// ---------------- masked+scaled softmax (valid keys are k >= q) ----------------
__global__ void softmax_kernel(float* __restrict__ scores) {
    int row = blockIdx.x;
    int q = row % SS;
    float* p = scores + (long long)row * SS;
    int tid = threadIdx.x;
    const float scale = 0.125f;
    float m = -1e30f;
    for (int k = q + tid; k < SS; k += 128) m = fmaxf(m, p[k] * scale);
    __shared__ float sh[128];
    sh[tid] = m; __syncthreads();
    for (int st = 64; st > 0; st >>= 1) { if (tid < st) sh[tid] = fmaxf(sh[tid], sh[tid+st]); __syncthreads(); }
    m = sh[0]; __syncthreads();
    float sum = 0.f;
    for (int k = q + tid; k < SS; k += 128) { float e = __expf(p[k]*scale - m); p[k] = e; sum += e; }
    sh[tid] = sum; __syncthreads();
    for (int st = 64; st > 0; st >>= 1) { if (tid < st) sh[tid] += sh[tid+st]; __syncthreads(); }
    float inv = 1.f / sh[0];
    for (int k = q + tid; k < SS; k += 128) p[k] *= inv;
    for (int k = tid; k < q; k += 128) p[k] = 0.f;
}

// ---------------- tf32 mma.sync GEMM v4 ----------------
// Template: TRANSB (B layout), NT (CTA N-tile: 128 or 256; blockDim = NT).
// A [M,K] row-major (lda). TRANSB=0: B [K,N] (ldb). TRANSB=1: B [N,K] (ldb).
// Modes: nsel==3 pointer-select | splitStride>0 split-K | zdiv>0 batched strides.
#define AROW 36
#define SA_W (128*AROW)

template<int TRANSB, int NT>
__global__ void __launch_bounds__(NT)
mma_gemm(const float* __restrict__ A,
         const float* B0, const float* B1, const float* B2,
         float* C0, float* C1, float* C2,
         const float* __restrict__ bias, const float* __restrict__ res,
         int K, int lda, int ldb, int ldc, int act, int nsel,
         long long splitStride, int rndOut, int zdiv,
         long long saz1, long long saz2, long long sbz1, long long sbz2,
         long long scz1, long long scz2)
{
    constexpr int BROW = TRANSB ? AROW : (NT + 8);
    constexpr int SB_W = TRANSB ? (NT * AROW) : (32 * BROW);
    constexpr int NWN = NT / 64;          // warp columns (2 or 4)

    extern __shared__ uint32_t smem[];
    uint32_t* SA[2] = { smem,          smem + SA_W };
    uint32_t* SB[2] = { smem + 2*SA_W, smem + 2*SA_W + SB_W };

    int tid  = threadIdx.x;
    int wid  = tid >> 5;
    int lane = tid & 31;
    int warp_m = wid / NWN;               // 0..1
    int warp_n = wid % NWN;               // 0..NWN-1
    int grp = lane >> 2, qid = lane & 3;

    int z = blockIdx.z;
    const float* Ap = A;
    const float* Bp = B0;
    float*       Cp = C0;
    if (nsel == 3) {
        Bp = (z == 0) ? B0 : ((z == 1) ? B1 : B2);
        Cp = (z == 0) ? C0 : ((z == 1) ? C1 : C2);
    } else if (splitStride > 0) {
        Ap = A  + (long long)z * K;
        Bp = B0 + (long long)z * K * ldb;
        Cp = C0 + (long long)z * splitStride;
    } else if (zdiv > 0) {
        int zd = z / zdiv, zm = z % zdiv;
        Ap = A  + zd*saz1 + zm*saz2;
        Bp = B0 + zd*sbz1 + zm*sbz2;
        Cp = C0 + zd*scz1 + zm*scz2;
    }

    long long m0 = (long long)blockIdx.y * 128;
    long long n0 = (long long)blockIdx.x * NT;

    // A staging: 128 x 32 = 1024 f4 -> 1024*8/NT per thread
    int a_r = tid >> 3;
    int a_c = (tid & 7) * 4;
    constexpr int A_IT = 1024 / (NT / 8) / 8;   // NT=128 -> 8 iters of 16 rows; NT=256 -> 4 iters of 32
    constexpr int A_ST = NT / 8;
    // B staging TRANSB=0: 32 x NT; TRANSB=1: NT x 32
    int b_r0 = TRANSB ? (tid >> 3) : (tid >> (NT == 128 ? 4 : 5));
    int b_c0 = TRANSB ? ((tid & 7) * 4) : ((tid & (NT == 128 ? 15 : 31)) * 8);

    float acc[32][4];
    #pragma unroll
    for (int t = 0; t < 32; t++)
        #pragma unroll
        for (int u = 0; u < 4; u++) acc[t][u] = 0.f;

    int NC = K >> 5;

    // ---- stage chunk into buffer ----
    auto stage = [&](int bufi, int kt) {
        #pragma unroll
        for (int i = 0; i < A_IT; i++) {
            int r = a_r + i * A_ST;
            CP_ASYNC16(smem_u32(SA[bufi] + r*AROW + a_c), Ap + (m0 + r) * lda + kt + a_c);
        }
        if (TRANSB) {
            #pragma unroll
            for (int i = 0; i < A_IT; i++) {
                int r = b_r0 + i * A_ST;
                CP_ASYNC16(smem_u32(SB[bufi] + r*AROW + b_c0), Bp + (n0 + r) * ldb + kt + b_c0);
            }
        } else {
            #pragma unroll
            for (int i = 0; i < 4; i++) {
                int r = b_r0 + i * (NT == 128 ? 8 : 8);
                const float* src = Bp + (long long)(kt + r) * ldb + n0 + b_c0;
                CP_ASYNC16(smem_u32(SB[bufi] + r*BROW + b_c0),     src);
                CP_ASYNC16(smem_u32(SB[bufi] + r*BROW + b_c0 + 4), src + 4);
            }
        }
        CP_COMMIT();
    };

    stage(0, 0);

    for (int c = 0; c < NC; c++) {
        int buf = c & 1;
        bool has_next = (c + 1) < NC;
        if (has_next) { stage(buf ^ 1, (c + 1) * 32); CP_WAIT1(); }
        else          { CP_WAIT0(); }
        __syncthreads();

        const uint32_t* As_ = SA[buf];
        const uint32_t* Bs_ = SB[buf];
        #pragma unroll
        for (int ks = 0; ks < 32; ks += 8) {
            uint32_t af[4][4], bf[8][2];
            #pragma unroll
            for (int i = 0; i < 4; i++) {
                int mr = warp_m*64 + i*16 + grp;
                af[i][0] = As_[(mr    )*AROW + ks + qid];
                af[i][1] = As_[(mr + 8)*AROW + ks + qid];
                af[i][2] = As_[(mr    )*AROW + ks + qid + 4];
                af[i][3] = As_[(mr + 8)*AROW + ks + qid + 4];
            }
            #pragma unroll
            for (int j = 0; j < 8; j++) {
                int nr = warp_n*64 + j*8 + grp;
                if (TRANSB) {
                    bf[j][0] = Bs_[nr*AROW + ks + qid];
                    bf[j][1] = Bs_[nr*AROW + ks + qid + 4];
                } else {
                    bf[j][0] = Bs_[(ks + qid    )*BROW + nr];
                    bf[j][1] = Bs_[(ks + qid + 4)*BROW + nr];
                }
            }
            #pragma unroll
            for (int i = 0; i < 4; i++)
                #pragma unroll
                for (int j = 0; j < 8; j++) {
                    int t = i*8 + j;
                    asm volatile(
                        "mma.sync.aligned.m16n8k8.row.col.f32.tf32.tf32.f32 "
                        "{%0,%1,%2,%3}, {%4,%5,%6,%7}, {%8,%9}, {%0,%1,%2,%3};"
                        : "+f"(acc[t][0]), "+f"(acc[t][1]), "+f"(acc[t][2]), "+f"(acc[t][3])
                        : "r"(af[i][0]), "r"(af[i][1]), "r"(af[i][2]), "r"(af[i][3]),
                          "r"(bf[j][0]), "r"(bf[j][1]));
                }
        }
        __syncthreads();
    }

    // ---- epilogue ----
    bool raw = (splitStride > 0);
    #pragma unroll
    for (int i = 0; i < 4; i++) {
        #pragma unroll
        for (int j = 0; j < 8; j++) {
            int t = i*8 + j;
            long long m = m0 + warp_m*64 + i*16 + grp;
            long long n = n0 + warp_n*64 + j*8 + qid*2;
            float bx = 0.f, by = 0.f;
            if (!raw && bias) { bx = bias[n]; by = bias[n+1]; }
            #pragma unroll
            for (int half = 0; half < 2; half++) {
                long long mm = m + half*8;
                float v0 = acc[t][half*2 + 0] + bx;
                float v1 = acc[t][half*2 + 1] + by;
                if (!raw) {
                    if (act == 1) { v0 = gelu_f(v0); v1 = gelu_f(v1); }
                    if (res) {
                        float2 r2 = *(const float2*)(res + mm*ldc + n);
                        v0 += r2.x; v1 += r2.y;
                    }
                    if (rndOut) { v0 = rndtf32(v0); v1 = rndtf32(v1); }
                }
                float2 o; o.x = v0; o.y = v1;
                *(float2*)(Cp + mm*ldc + n) = o;
            }
        }
    }
}

#define SMEM_T0_128 ((2*SA_W + 2*32*136)*4)
#define SMEM_T1_128 ((2*SA_W + 2*128*AROW)*4)
#define SMEM_T0_256 ((2*SA_W + 2*32*264)*4)

// ---------------- SIMT SGEMM (PV only): 64x64 tile, 128 threads ----------------
__global__ void __launch_bounds__(128)
pv_gemm(const float* __restrict__ A, const float* __restrict__ Bm,
        float* __restrict__ C, int zdiv, int rndOut,
        long long sa2, long long sb1, long long sb2, long long sc1, long long sc2)
{
    __shared__ float As[2][16][68];
    __shared__ float Bs[2][16][68];

    int z = blockIdx.z;
    int zd = z / zdiv, zm = z % zdiv;
    const float* Ab = A  + (long long)z * sa2;
    const float* Bb = Bm + zd*sb1 + zm*sb2;
    float*       Cb = C  + zd*sc1 + zm*sc2;
    const int K = SS, lda = SS, ldb = DD, ldc = DD;

    int tid = threadIdx.x;
    int m0 = blockIdx.y * 64;
    int n0 = blockIdx.x * 64;

    int a_r0 = tid >> 2;
    int a_kg = (tid & 3) * 4;
    int b_k0 = tid >> 4;
    int b_n4 = (tid & 15) * 4;
    int tx = tid & 15;
    int ty = tid >> 4;

    float acc[8][4];
    #pragma unroll
    for (int i = 0; i < 8; i++)
        #pragma unroll
        for (int j = 0; j < 4; j++) acc[i][j] = 0.f;

    float4 ra0, ra1, rb0, rb1;
    ra0 = *(const float4*)(Ab + (long long)(m0 + a_r0     )*lda + a_kg);
    ra1 = *(const float4*)(Ab + (long long)(m0 + a_r0 + 32)*lda + a_kg);
    rb0 = *(const float4*)(Bb + (long long)(b_k0    )*ldb + n0 + b_n4);
    rb1 = *(const float4*)(Bb + (long long)(b_k0 + 8)*ldb + n0 + b_n4);
    {
        As[0][a_kg+0][a_r0] = ra0.x; As[0][a_kg+1][a_r0] = ra0.y;
        As[0][a_kg+2][a_r0] = ra0.z; As[0][a_kg+3][a_r0] = ra0.w;
        As[0][a_kg+0][a_r0+32] = ra1.x; As[0][a_kg+1][a_r0+32] = ra1.y;
        As[0][a_kg+2][a_r0+32] = ra1.z; As[0][a_kg+3][a_r0+32] = ra1.w;
        *(float4*)&Bs[0][b_k0  ][b_n4] = rb0;
        *(float4*)&Bs[0][b_k0+8][b_n4] = rb1;
    }
    __syncthreads();

    int buf = 0;
    for (int kt = 0; kt < K; kt += 16) {
        bool has_next = (kt + 16) < K;
        if (has_next) {
            int kn = kt + 16;
            ra0 = *(const float4*)(Ab + (long long)(m0 + a_r0     )*lda + kn + a_kg);
            ra1 = *(const float4*)(Ab + (long long)(m0 + a_r0 + 32)*lda + kn + a_kg);
            rb0 = *(const float4*)(Bb + (long long)(kn + b_k0    )*ldb + n0 + b_n4);
            rb1 = *(const float4*)(Bb + (long long)(kn + b_k0 + 8)*ldb + n0 + b_n4);
        }
        #pragma unroll
        for (int k = 0; k < 16; k++) {
            float4 x0 = *(const float4*)&As[buf][k][ty*8];
            float4 x1 = *(const float4*)&As[buf][k][ty*8 + 4];
            float4 y  = *(const float4*)&Bs[buf][k][tx*4];
            float am[8] = {x0.x, x0.y, x0.z, x0.w, x1.x, x1.y, x1.z, x1.w};
            #pragma unroll
            for (int i = 0; i < 8; i++) {
                acc[i][0] += am[i]*y.x; acc[i][1] += am[i]*y.y;
                acc[i][2] += am[i]*y.z; acc[i][3] += am[i]*y.w;
            }
        }
        if (has_next) {
            int nb = buf ^ 1;
            As[nb][a_kg+0][a_r0] = ra0.x; As[nb][a_kg+1][a_r0] = ra0.y;
            As[nb][a_kg+2][a_r0] = ra0.z; As[nb][a_kg+3][a_r0] = ra0.w;
            As[nb][a_kg+0][a_r0+32] = ra1.x; As[nb][a_kg+1][a_r0+32] = ra1.y;
            As[nb][a_kg+2][a_r0+32] = ra1.z; As[nb][a_kg+3][a_r0+32] = ra1.w;
            *(float4*)&Bs[nb][b_k0  ][b_n4] = rb0;
            *(float4*)&Bs[nb][b_k0+8][b_n4] = rb1;
            __syncthreads();
            buf = nb;
        }
    }

    int n = n0 + tx*4;
    #pragma unroll
    for (int i = 0; i < 8; i++) {
        int m = m0 + ty*8 + i;
        float4 v = {acc[i][0], acc[i][1], acc[i][2], acc[i][3]};
        if (rndOut) { v.x = rndtf32(v.x); v.y = rndtf32(v.y); v.z = rndtf32(v.z); v.w = rndtf32(v.w); }
        *(float4*)(Cb + (long long)m*ldc + n) = v;
    }
}

// ---- launch helpers ----
static void launch_mma(const float* A, const float* B0, const float* B1, const float* B2,
                       float* C0, float* C1, float* C2,
                       const float* bias, const float* res,
                       int M, int N, int K, int ldb, int ldc, int act, int nsel, int rndOut)
{
    dim3 grid(N/128, M/128, nsel), blk(128);
    mma_gemm<0,128><<<grid, blk, SMEM_T0_128>>>(A, B0, B1, B2, C0, C1, C2, bias, res,
        K, K, ldb, ldc, act, nsel, 0, rndOut, 0, 0,0,0,0,0,0);
}

static void launch_mma_wide(const float* A, const float* B, float* C,
                            const float* bias, int M, int N, int K, int ldb, int ldc)
{
    dim3 grid(N/256, M/128, 1), blk(256);
    mma_gemm<0,256><<<grid, blk, SMEM_T0_256>>>(A, B, B, B, C, C, C, bias, 0,
        K, K, ldb, ldc, 0, 1, 0, 0, 0, 0,0,0,0,0,0);
}

static void launch_mma_split4(const float* A, const float* B, float* part,
                              const float* bias, const float* res, float* out,
                              int M, int N, int K, int act, int rndOut)
{
    int Ks = K / 4;
    dim3 grid(N/128, M/128, 4), blk(128);
    mma_gemm<0,128><<<grid, blk, SMEM_T0_128>>>(A, B, B, B, part, part, part, 0, 0,
        Ks, K, N, N, 0, 1, (long long)M*N, 0, 0, 0,0,0,0,0,0);
    int MN = M * N;
    reduce4_kernel<<<(MN + 255)/256, 256>>>(part, bias, res, out, MN, N, act, rndOut);
}

static void launch_qk(const float* Q, const float* Kp, float* scores)
{
    const long long SD = (long long)SS * DD;
    const long long SSs = (long long)SS * SS;
    dim3 grid(SS/128, SS/128, BB*HH), blk(128);
    mma_gemm<1,128><<<grid, blk, SMEM_T1_128>>>(Q, Kp, Kp, Kp, scores, scores, scores, 0, 0,
        HDIM, DD, DD, SS, 0, 1, 0, 0, HH,
        SD, HDIM, SD, HDIM, (long long)HH*SSs, SSs);
}

extern "C" void kernel_launch(void* const* d_in, const int* in_sizes, int n_in,
                              void* d_out, int out_size)
{
    const int*   x   = (const int*)  d_in[0];
    const float* tok = (const float*)d_in[1];
    const float* pos = (const float*)d_in[2];
    const float* n1s = (const float*)d_in[3];
    const float* n1b = (const float*)d_in[4];
    const float* n2s = (const float*)d_in[5];
    const float* n2b = (const float*)d_in[6];
    const float* wq  = (const float*)d_in[7];
    const float* wk  = (const float*)d_in[8];
    const float* wv  = (const float*)d_in[9];
    const float* wo  = (const float*)d_in[10];
    const float* bo  = (const float*)d_in[11];
    const float* w1  = (const float*)d_in[12];
    const float* b1  = (const float*)d_in[13];
    const float* w2  = (const float*)d_in[14];
    const float* b2  = (const float*)d_in[15];
    const float* fs  = (const float*)d_in[16];
    const float* fb  = (const float*)d_in[17];
    const float* hw  = (const float*)d_in[18];
    const float* hb  = (const float*)d_in[19];
    float* out = (float*)d_out;

    cudaFuncSetAttribute(mma_gemm<0,128>, cudaFuncAttributeMaxDynamicSharedMemorySize, SMEM_T0_128);
    cudaFuncSetAttribute(mma_gemm<1,128>, cudaFuncAttributeMaxDynamicSharedMemorySize, SMEM_T1_128);
    cudaFuncSetAttribute(mma_gemm<0,256>, cudaFuncAttributeMaxDynamicSharedMemorySize, SMEM_T0_256);

    float *h, *hn, *gq, *gk, *gv, *ctx, *ffn, *sc, *part;
    float *wqR, *wkR, *wvR, *woR, *w1R, *w2R, *hwR;
    cudaGetSymbolAddress((void**)&h,   g_h);
    cudaGetSymbolAddress((void**)&hn,  g_hn);
    cudaGetSymbolAddress((void**)&gq,  g_q);
    cudaGetSymbolAddress((void**)&gk,  g_k);
    cudaGetSymbolAddress((void**)&gv,  g_v);
    cudaGetSymbolAddress((void**)&ctx, g_ctx);
    cudaGetSymbolAddress((void**)&ffn, g_ffn);
    cudaGetSymbolAddress((void**)&sc,  g_sc);
    cudaGetSymbolAddress((void**)&part, g_part);
    cudaGetSymbolAddress((void**)&wqR, g_wqR);
    cudaGetSymbolAddress((void**)&wkR, g_wkR);
    cudaGetSymbolAddress((void**)&wvR, g_wvR);
    cudaGetSymbolAddress((void**)&woR, g_woR);
    cudaGetSymbolAddress((void**)&w1R, g_w1R);
    cudaGetSymbolAddress((void**)&w2R, g_w2R);
    cudaGetSymbolAddress((void**)&hwR, g_hwR);

    const int M = BB * SS;
    const long long SD  = (long long)SS * DD;
    const long long SSs = (long long)SS * SS;

    long long n4dd = (long long)NLAYER*DD*DD/4;
    // launches 0-2: QKV rounds; 3: embed; 4: norm; 5: QKV mma (profiled)
    round_kernel<<<(unsigned)((n4dd+255)/256), 256>>>(wq, wqR, n4dd);
    round_kernel<<<(unsigned)((n4dd+255)/256), 256>>>(wk, wkR, n4dd);
    round_kernel<<<(unsigned)((n4dd+255)/256), 256>>>(wv, wvR, n4dd);
    embed_kernel<<<(BB*SS*DD + 255)/256, 256>>>(x, tok, pos, h);
    norm_kernel<<<M, 256>>>(h, n1s, n1b, hn);
    launch_mma(hn, wqR, wkR, wvR, gq, gk, gv, 0, 0, M, DD, DD, DD, DD, 0, 3, 1);
    {
        long long n4;
        round_kernel<<<(unsigned)((n4dd+255)/256), 256>>>(wo, woR, n4dd);
        n4 = (long long)NLAYER*DD*DFF/4;
        round_kernel<<<(unsigned)((n4+255)/256), 256>>>(w1, w1R, n4);
        round_kernel<<<(unsigned)((n4+255)/256), 256>>>(w2, w2R, n4);
        n4 = (long long)VV*DD/4;
        round_kernel<<<(unsigned)((n4+255)/256), 256>>>(hw, hwR, n4);
    }

    for (int l = 0; l < NLAYER; l++) {
        if (l > 0) {
            norm_kernel<<<M, 256>>>(h, n1s + l*DD, n1b + l*DD, hn);
            launch_mma(hn, wqR + (long long)l*DD*DD, wkR + (long long)l*DD*DD, wvR + (long long)l*DD*DD,
                       gq, gk, gv, 0, 0, M, DD, DD, DD, DD, 0, 3, 1);
        }

        // scores = Q . K^T (tensor, batched)
        launch_qk(gq, gk, sc);

        softmax_kernel<<<BB*HH*SS, 128>>>(sc);

        // ctx = P @ V (SIMT fp32; output rounded -> feeds O-proj mma)
        {
            dim3 grid(1, SS/64, BB*HH), blk(128);
            pv_gemm<<<grid, blk>>>(sc, gv, ctx, HH, 1,
                                   SSs, SD, HDIM, SD, HDIM);
        }

        // x = res + ctx @ wo + bo (tensor, split-K x4)
        launch_mma_split4(ctx, woR + (long long)l*DD*DD, part, bo + l*DD, h, h,
                          M, DD, DD, 0, 0);

        norm_kernel<<<M, 256>>>(h, n2s + l*DD, n2b + l*DD, hn);

        // ffn = gelu(hn @ w1 + b1) (tensor; output rounded)
        launch_mma(hn, w1R + (long long)l*DD*DFF, 0, 0, ffn, 0, 0,
                   b1 + l*DFF, 0, M, DFF, DD, DFF, DFF, 1, 1, 1);

        // x = res + ffn @ w2 + b2 (tensor, split-K x4)
        launch_mma_split4(ffn, w2R + (long long)l*DFF*DD, part, b2 + l*DD, h, h,
                          M, DD, DFF, 0, 0);
    }

    norm_kernel<<<M, 256>>>(h, fs, fb, hn);
    // logits = hn @ head_w + head_b (tensor, 256-wide tile)
    launch_mma_wide(hn, hwR, out, hb, M, VV, DD, VV, VV);
}

// round 9
// speedup vs baseline: 3.0466x; 1.0655x over previous
#include <cuda_runtime.h>
#include <math.h>
#include <stdint.h>

#define BB 2
#define SS 512
#define DD 768
#define HH 12
#define NLAYER 6
#define VV 32000
#define HDIM 64
#define DFF 3072
#define EPSF 1e-6f

// ---------------- scratch (device globals; no allocs allowed) ----------------
__device__ float g_h  [BB*SS*DD];
__device__ float g_hn [BB*SS*DD];
__device__ float g_q  [BB*SS*DD];
__device__ float g_k  [BB*SS*DD];
__device__ float g_v  [BB*SS*DD];
__device__ float g_ctx[BB*SS*DD];
__device__ float g_ffn[BB*SS*DFF];
__device__ float g_sc [BB*HH*SS*SS];
__device__ float g_part[4*BB*SS*DD];
// tf32-rounded weights (ORIGINAL [K,N] layouts)
__device__ float g_wqR[NLAYER*DD*DD];
__device__ float g_wkR[NLAYER*DD*DD];
__device__ float g_wvR[NLAYER*DD*DD];
__device__ float g_woR[NLAYER*DD*DD];
__device__ float g_w1R[NLAYER*DD*DFF];
__device__ float g_w2R[NLAYER*DFF*DD];
__device__ float g_hwR[(long long)VV*DD];

__device__ __forceinline__ uint32_t f2tf32(float x) {
    uint32_t r;
    asm("cvt.rna.tf32.f32 %0, %1;" : "=r"(r) : "f"(x));
    return r;
}
__device__ __forceinline__ float rndtf32(float x) { return __uint_as_float(f2tf32(x)); }

__device__ __forceinline__ float gelu_f(float v) {
    float t = v + 0.044715f * v * v * v;
    return 0.5f * v * (1.0f + tanhf(0.7978845608028654f * t));
}
__device__ __forceinline__ uint32_t smem_u32(const void* p) {
    uint32_t a;
    asm("{ .reg .u64 t; cvta.to.shared.u64 t, %1; cvt.u32.u64 %0, t; }" : "=r"(a) : "l"(p));
    return a;
}
#define CP_ASYNC16(dst, src) \
    asm volatile("cp.async.cg.shared.global [%0], [%1], 16;" :: "r"(dst), "l"(src))
#define CP_COMMIT() asm volatile("cp.async.commit_group;" ::: "memory")
#define CP_WAIT0() asm volatile("cp.async.wait_group 0;" ::: "memory")
#define CP_WAIT1() asm volatile("cp.async.wait_group 1;" ::: "memory")

// ---------------- embedding ----------------
__global__ void embed_kernel(const int* __restrict__ x, const float* __restrict__ tok,
                             const float* __restrict__ pos, float* __restrict__ out) {
    int idx = blockIdx.x * blockDim.x + threadIdx.x;
    if (idx >= BB*SS*DD) return;
    int d  = idx % DD;
    int bs = idx / DD;
    int s  = bs % SS;
    out[idx] = tok[(long long)x[bs]*DD + d] + pos[s*DD + d];
}

// ---------------- tf32 round copy ----------------
__global__ void round_kernel(const float* __restrict__ in, float* __restrict__ out, long long n4) {
    long long i = (long long)blockIdx.x * blockDim.x + threadIdx.x;
    if (i >= n4) return;
    float4 v = ((const float4*)in)[i];
    v.x = rndtf32(v.x); v.y = rndtf32(v.y); v.z = rndtf32(v.z); v.w = rndtf32(v.w);
    ((float4*)out)[i] = v;
}

// ---------------- "DummyNorm" (standalone; first layer only) ----------------
__global__ void norm_kernel(const float* __restrict__ x, const float* __restrict__ sc,
                            const float* __restrict__ bi, float* __restrict__ y) {
    int row = blockIdx.x;
    const float* xr = x + (long long)row * DD;
    float* yr = y + (long long)row * DD;
    int tid = threadIdx.x;
    float sum = 0.f, sq = 0.f;
    for (int i = tid; i < DD; i += 256) { float v = xr[i]; sum += v; sq += v*v; }
    __shared__ float s1[256], s2[256];
    s1[tid] = sum; s2[tid] = sq; __syncthreads();
    for (int st = 128; st > 0; st >>= 1) {
        if (tid < st) { s1[tid] += s1[tid+st]; s2[tid] += s2[tid+st]; }
        __syncthreads();
    }
    float mean = s1[0] / (float)DD;
    float var  = (s2[0] - (float)DD * mean * mean) / (float)(DD - 1);
    float inv  = 1.f / (sqrtf(fmaxf(var, 0.f)) + EPSF);
    for (int i = tid; i < DD; i += 256)
        yr[i] = rndtf32(sc[i] * (xr[i] - mean) * inv + bi[i]);
}

// ---------------- fused split-K reduce + residual + DummyNorm ----------------
// h[row] = res[row] + (sum_4 part) + bias ; hn[row] = rnd(norm(h[row]))
__global__ void reduce_norm_kernel(const float* __restrict__ part, const float* __restrict__ bias,
                                   const float* __restrict__ res, float* __restrict__ hout,
                                   const float* __restrict__ ns, const float* __restrict__ nb,
                                   float* __restrict__ hn, int MN) {
    int row = blockIdx.x;
    int tid = threadIdx.x;
    __shared__ float s1[256], s2[256];
    __shared__ float vrow[DD];
    float sum = 0.f, sq = 0.f;
    for (int i = tid; i < DD; i += 256) {
        int idx = row * DD + i;
        float v = part[idx] + part[idx + MN] + part[idx + 2*MN] + part[idx + 3*MN]
                + bias[i] + res[idx];
        vrow[i] = v; sum += v; sq += v*v;
    }
    s1[tid] = sum; s2[tid] = sq; __syncthreads();
    for (int st = 128; st > 0; st >>= 1) {
        if (tid < st) { s1[tid] += s1[tid+st]; s2[tid] += s2[tid+st]; }
        __syncthreads();
    }
    float mean = s1[0] / (float)DD;
    float var  = (s2[0] - (float)DD * mean * mean) / (float)(DD - 1);
    float inv  = 1.f / (sqrtf(fmaxf(var, 0.f)) + EPSF);
    for (int i = tid; i < DD; i += 256) {
        float v = vrow[i];
        int idx = row * DD + i;
        hout[idx] = v;
        hn[idx] = rndtf32(ns[i] * (v - mean) * inv + nb[i]);
    }
}

// ---------------- masked+scaled softmax; output tf32-rounded (feeds PV mma) ----------------
__global__ void softmax_kernel(float* __restrict__ scores) {
    int row = blockIdx.x;
    int q = row % SS;
    float* p = scores + (long long)row * SS;
    int tid = threadIdx.x;
    const float scale = 0.125f;
    float m = -1e30f;
    for (int k = q + tid; k < SS; k += 128) m = fmaxf(m, p[k] * scale);
    __shared__ float sh[128];
    sh[tid] = m; __syncthreads();
    for (int st = 64; st > 0; st >>= 1) { if (tid < st) sh[tid] = fmaxf(sh[tid], sh[tid+st]); __syncthreads(); }
    m = sh[0]; __syncthreads();
    float sum = 0.f;
    for (int k = q + tid; k < SS; k += 128) { float e = __expf(p[k]*scale - m); p[k] = e; sum += e; }
    sh[tid] = sum; __syncthreads();
    for (int st = 64; st > 0; st >>= 1) { if (tid < st) sh[tid] += sh[tid+st]; __syncthreads(); }
    float inv = 1.f / sh[0];
    for (int k = q + tid; k < SS; k += 128) p[k] = rndtf32(p[k] * inv);
    for (int k = tid; k < q; k += 128) p[k] = 0.f;
}

// ---------------- tf32 mma.sync GEMM v5 ----------------
// Template: TRANSB (B layout), NT (CTA N-tile 64/128/256; blockDim = NT).
// A [M,K] (lda). TRANSB=0: B [K,N] (ldb). TRANSB=1: B [N,K] (ldb).
// Modes: nsel==3 pointer-select | splitStride>0 split-K | zdiv>0 batched strides.
#define AROW 36
#define SA_W (128*AROW)

template<int TRANSB, int NT>
__global__ void __launch_bounds__(NT)
mma_gemm(const float* __restrict__ A,
         const float* B0, const float* B1, const float* B2,
         float* C0, float* C1, float* C2,
         const float* __restrict__ bias, const float* __restrict__ res,
         int K, int lda, int ldb, int ldc, int act, int nsel,
         long long splitStride, int rndOut, int zdiv,
         long long saz1, long long saz2, long long sbz1, long long sbz2,
         long long scz1, long long scz2)
{
    constexpr int BROW = TRANSB ? AROW : (NT + 8);
    constexpr int SB_W = TRANSB ? (NT * AROW) : (32 * BROW);
    constexpr int NWN = NT / 64;

    extern __shared__ uint32_t smem[];
    uint32_t* SA[2] = { smem,          smem + SA_W };
    uint32_t* SB[2] = { smem + 2*SA_W, smem + 2*SA_W + SB_W };

    int tid  = threadIdx.x;
    int wid  = tid >> 5;
    int lane = tid & 31;
    int warp_m = wid / NWN;
    int warp_n = wid % NWN;
    int grp = lane >> 2, qid = lane & 3;

    int z = blockIdx.z;
    const float* Ap = A;
    const float* Bp = B0;
    float*       Cp = C0;
    if (nsel == 3) {
        Bp = (z == 0) ? B0 : ((z == 1) ? B1 : B2);
        Cp = (z == 0) ? C0 : ((z == 1) ? C1 : C2);
    } else if (splitStride > 0) {
        Ap = A  + (long long)z * K;
        Bp = B0 + (long long)z * K * ldb;
        Cp = C0 + (long long)z * splitStride;
    } else if (zdiv > 0) {
        int zd = z / zdiv, zm = z % zdiv;
        Ap = A  + zd*saz1 + zm*saz2;
        Bp = B0 + zd*sbz1 + zm*sbz2;
        Cp = C0 + zd*scz1 + zm*scz2;
    }

    long long m0 = (long long)blockIdx.y * 128;
    long long n0 = (long long)blockIdx.x * NT;

    // A staging: 128 rows x 32 k = 1024 f4
    int a_r = tid >> 3;
    int a_c = (tid & 7) * 4;
    constexpr int A_ST = NT / 8;
    constexpr int A_IT = 128 / A_ST;
    // B staging: TRANSB=0: 32 x NT (NT/8 threads per row); TRANSB=1: NT x 32
    constexpr int TPBR = NT / 8;
    int b_r0 = TRANSB ? (tid >> 3) : (tid / TPBR);
    int b_c0 = TRANSB ? ((tid & 7) * 4) : ((tid % TPBR) * 8);

    float acc[32][4];
    #pragma unroll
    for (int t = 0; t < 32; t++)
        #pragma unroll
        for (int u = 0; u < 4; u++) acc[t][u] = 0.f;

    int NC = K >> 5;

    auto stage = [&](int bufi, int kt) {
        #pragma unroll
        for (int i = 0; i < A_IT; i++) {
            int r = a_r + i * A_ST;
            CP_ASYNC16(smem_u32(SA[bufi] + r*AROW + a_c), Ap + (m0 + r) * lda + kt + a_c);
        }
        if (TRANSB) {
            #pragma unroll
            for (int i = 0; i < A_IT; i++) {
                int r = b_r0 + i * A_ST;
                CP_ASYNC16(smem_u32(SB[bufi] + r*AROW + b_c0), Bp + (n0 + r) * ldb + kt + b_c0);
            }
        } else {
            #pragma unroll
            for (int i = 0; i < 4; i++) {
                int r = b_r0 + i * 8;
                const float* src = Bp + (long long)(kt + r) * ldb + n0 + b_c0;
                CP_ASYNC16(smem_u32(SB[bufi] + r*BROW + b_c0),     src);
                CP_ASYNC16(smem_u32(SB[bufi] + r*BROW + b_c0 + 4), src + 4);
            }
        }
        CP_COMMIT();
    };

    stage(0, 0);

    for (int c = 0; c < NC; c++) {
        int buf = c & 1;
        bool has_next = (c + 1) < NC;
        if (has_next) { stage(buf ^ 1, (c + 1) * 32); CP_WAIT1(); }
        else          { CP_WAIT0(); }
        __syncthreads();

        const uint32_t* As_ = SA[buf];
        const uint32_t* Bs_ = SB[buf];
        #pragma unroll
        for (int ks = 0; ks < 32; ks += 8) {
            uint32_t af[4][4], bf[8][2];
            #pragma unroll
            for (int i = 0; i < 4; i++) {
                int mr = warp_m*64 + i*16 + grp;
                af[i][0] = As_[(mr    )*AROW + ks + qid];
                af[i][1] = As_[(mr + 8)*AROW + ks + qid];
                af[i][2] = As_[(mr    )*AROW + ks + qid + 4];
                af[i][3] = As_[(mr + 8)*AROW + ks + qid + 4];
            }
            #pragma unroll
            for (int j = 0; j < 8; j++) {
                int nr = warp_n*64 + j*8 + grp;
                if (TRANSB) {
                    bf[j][0] = Bs_[nr*AROW + ks + qid];
                    bf[j][1] = Bs_[nr*AROW + ks + qid + 4];
                } else {
                    bf[j][0] = Bs_[(ks + qid    )*BROW + nr];
                    bf[j][1] = Bs_[(ks + qid + 4)*BROW + nr];
                }
            }
            #pragma unroll
            for (int i = 0; i < 4; i++)
                #pragma unroll
                for (int j = 0; j < 8; j++) {
                    int t = i*8 + j;
                    asm volatile(
                        "mma.sync.aligned.m16n8k8.row.col.f32.tf32.tf32.f32 "
                        "{%0,%1,%2,%3}, {%4,%5,%6,%7}, {%8,%9}, {%0,%1,%2,%3};"
                        : "+f"(acc[t][0]), "+f"(acc[t][1]), "+f"(acc[t][2]), "+f"(acc[t][3])
                        : "r"(af[i][0]), "r"(af[i][1]), "r"(af[i][2]), "r"(af[i][3]),
                          "r"(bf[j][0]), "r"(bf[j][1]));
                }
        }
        __syncthreads();
    }

    // ---- epilogue ----
    bool raw = (splitStride > 0);
    #pragma unroll
    for (int i = 0; i < 4; i++) {
        #pragma unroll
        for (int j = 0; j < 8; j++) {
            int t = i*8 + j;
            long long m = m0 + warp_m*64 + i*16 + grp;
            long long n = n0 + warp_n*64 + j*8 + qid*2;
            float bx = 0.f, by = 0.f;
            if (!raw && bias) { bx = bias[n]; by = bias[n+1]; }
            #pragma unroll
            for (int half = 0; half < 2; half++) {
                long long mm = m + half*8;
                float v0 = acc[t][half*2 + 0] + bx;
                float v1 = acc[t][half*2 + 1] + by;
                if (!raw) {
                    if (act == 1) { v0 = gelu_f(v0); v1 = gelu_f(v1); }
                    if (res) {
                        float2 r2 = *(const float2*)(res + mm*ldc + n);
                        v0 += r2.x; v1 += r2.y;
                    }
                    if (rndOut) { v0 = rndtf32(v0); v1 = rndtf32(v1); }
                }
                float2 o; o.x = v0; o.y = v1;
                *(float2*)(Cp + mm*ldc + n) = o;
            }
        }
    }
}

#define SMEM_T0_64  ((2*SA_W + 2*32*72)*4)
#define SMEM_T0_128 ((2*SA_W + 2*32*136)*4)
#define SMEM_T1_128 ((2*SA_W + 2*128*AROW)*4)
#define SMEM_T0_256 ((2*SA_W + 2*32*264)*4)

// ---- launch helpers ----
static void launch_mma(const float* A, const float* B0, const float* B1, const float* B2,
                       float* C0, float* C1, float* C2,
                       const float* bias, const float* res,
                       int M, int N, int K, int ldb, int ldc, int act, int nsel, int rndOut)
{
    dim3 grid(N/128, M/128, nsel), blk(128);
    mma_gemm<0,128><<<grid, blk, SMEM_T0_128>>>(A, B0, B1, B2, C0, C1, C2, bias, res,
        K, K, ldb, ldc, act, nsel, 0, rndOut, 0, 0,0,0,0,0,0);
}

static void launch_mma_wide(const float* A, const float* B, float* C,
                            const float* bias, int M, int N, int K, int ldb, int ldc)
{
    dim3 grid(N/256, M/128, 1), blk(256);
    mma_gemm<0,256><<<grid, blk, SMEM_T0_256>>>(A, B, B, B, C, C, C, bias, 0,
        K, K, ldb, ldc, 0, 1, 0, 0, 0, 0,0,0,0,0,0);
}

static void launch_mma_split4(const float* A, const float* B, float* part,
                              int M, int N, int K)
{
    int Ks = K / 4;
    dim3 grid(N/128, M/128, 4), blk(128);
    mma_gemm<0,128><<<grid, blk, SMEM_T0_128>>>(A, B, B, B, part, part, part, 0, 0,
        Ks, K, N, N, 0, 1, (long long)M*N, 0, 0, 0,0,0,0,0,0);
}

static void launch_qk(const float* Q, const float* Kp, float* scores)
{
    const long long SD = (long long)SS * DD;
    const long long SSs = (long long)SS * SS;
    dim3 grid(SS/128, SS/128, BB*HH), blk(128);
    mma_gemm<1,128><<<grid, blk, SMEM_T1_128>>>(Q, Kp, Kp, Kp, scores, scores, scores, 0, 0,
        HDIM, DD, DD, SS, 0, 1, 0, 0, HH,
        SD, HDIM, SD, HDIM, (long long)HH*SSs, SSs);
}

static void launch_pv(const float* P, const float* V, float* ctx)
{
    const long long SD = (long long)SS * DD;
    const long long SSs = (long long)SS * SS;
    dim3 grid(1, SS/128, BB*HH), blk(64);
    // A = P (scores), per-z offset z*SSs via zdiv strides; B = V [S,DD] head cols; C = ctx
    mma_gemm<0,64><<<grid, blk, SMEM_T0_64>>>(P, V, V, V, ctx, ctx, ctx, 0, 0,
        SS, SS, DD, DD, 0, 1, 0, 1, HH,
        (long long)HH*SSs, SSs, SD, HDIM, SD, HDIM);
}

extern "C" void kernel_launch(void* const* d_in, const int* in_sizes, int n_in,
                              void* d_out, int out_size)
{
    const int*   x   = (const int*)  d_in[0];
    const float* tok = (const float*)d_in[1];
    const float* pos = (const float*)d_in[2];
    const float* n1s = (const float*)d_in[3];
    const float* n1b = (const float*)d_in[4];
    const float* n2s = (const float*)d_in[5];
    const float* n2b = (const float*)d_in[6];
    const float* wq  = (const float*)d_in[7];
    const float* wk  = (const float*)d_in[8];
    const float* wv  = (const float*)d_in[9];
    const float* wo  = (const float*)d_in[10];
    const float* bo  = (const float*)d_in[11];
    const float* w1  = (const float*)d_in[12];
    const float* b1  = (const float*)d_in[13];
    const float* w2  = (const float*)d_in[14];
    const float* b2  = (const float*)d_in[15];
    const float* fs  = (const float*)d_in[16];
    const float* fb  = (const float*)d_in[17];
    const float* hw  = (const float*)d_in[18];
    const float* hb  = (const float*)d_in[19];
    float* out = (float*)d_out;

    cudaFuncSetAttribute(mma_gemm<0,64>,  cudaFuncAttributeMaxDynamicSharedMemorySize, SMEM_T0_64);
    cudaFuncSetAttribute(mma_gemm<0,128>, cudaFuncAttributeMaxDynamicSharedMemorySize, SMEM_T0_128);
    cudaFuncSetAttribute(mma_gemm<1,128>, cudaFuncAttributeMaxDynamicSharedMemorySize, SMEM_T1_128);
    cudaFuncSetAttribute(mma_gemm<0,256>, cudaFuncAttributeMaxDynamicSharedMemorySize, SMEM_T0_256);

    float *h, *hn, *gq, *gk, *gv, *ctx, *ffn, *sc, *part;
    float *wqR, *wkR, *wvR, *woR, *w1R, *w2R, *hwR;
    cudaGetSymbolAddress((void**)&h,   g_h);
    cudaGetSymbolAddress((void**)&hn,  g_hn);
    cudaGetSymbolAddress((void**)&gq,  g_q);
    cudaGetSymbolAddress((void**)&gk,  g_k);
    cudaGetSymbolAddress((void**)&gv,  g_v);
    cudaGetSymbolAddress((void**)&ctx, g_ctx);
    cudaGetSymbolAddress((void**)&ffn, g_ffn);
    cudaGetSymbolAddress((void**)&sc,  g_sc);
    cudaGetSymbolAddress((void**)&part, g_part);
    cudaGetSymbolAddress((void**)&wqR, g_wqR);
    cudaGetSymbolAddress((void**)&wkR, g_wkR);
    cudaGetSymbolAddress((void**)&wvR, g_wvR);
    cudaGetSymbolAddress((void**)&woR, g_woR);
    cudaGetSymbolAddress((void**)&w1R, g_w1R);
    cudaGetSymbolAddress((void**)&w2R, g_w2R);
    cudaGetSymbolAddress((void**)&hwR, g_hwR);

    const int M = BB * SS;
    const int MN_DD = M * DD;

    long long n4dd = (long long)NLAYER*DD*DD/4;
    // launches 0-2: QKV rounds; 3: embed; 4: norm; 5: QKV mma (profiled)
    round_kernel<<<(unsigned)((n4dd+255)/256), 256>>>(wq, wqR, n4dd);
    round_kernel<<<(unsigned)((n4dd+255)/256), 256>>>(wk, wkR, n4dd);
    round_kernel<<<(unsigned)((n4dd+255)/256), 256>>>(wv, wvR, n4dd);
    embed_kernel<<<(BB*SS*DD + 255)/256, 256>>>(x, tok, pos, h);
    norm_kernel<<<M, 256>>>(h, n1s, n1b, hn);
    launch_mma(hn, wqR, wkR, wvR, gq, gk, gv, 0, 0, M, DD, DD, DD, DD, 0, 3, 1);
    {
        long long n4;
        round_kernel<<<(unsigned)((n4dd+255)/256), 256>>>(wo, woR, n4dd);
        n4 = (long long)NLAYER*DD*DFF/4;
        round_kernel<<<(unsigned)((n4+255)/256), 256>>>(w1, w1R, n4);
        round_kernel<<<(unsigned)((n4+255)/256), 256>>>(w2, w2R, n4);
        n4 = (long long)VV*DD/4;
        round_kernel<<<(unsigned)((n4+255)/256), 256>>>(hw, hwR, n4);
    }

    for (int l = 0; l < NLAYER; l++) {
        if (l > 0) {
            // hn was produced by the previous layer's fused reduce_norm
            launch_mma(hn, wqR + (long long)l*DD*DD, wkR + (long long)l*DD*DD, wvR + (long long)l*DD*DD,
                       gq, gk, gv, 0, 0, M, DD, DD, DD, DD, 0, 3, 1);
        }

        // scores = Q . K^T (tensor, batched)
        launch_qk(gq, gk, sc);

        softmax_kernel<<<BB*HH*SS, 128>>>(sc);

        // ctx = P @ V (tensor, batched; output rounded)
        launch_pv(sc, gv, ctx);

        // O-proj split-K x4 -> partials; fused reduce + residual + norm2 -> h, hn
        launch_mma_split4(ctx, woR + (long long)l*DD*DD, part, M, DD, DD);
        reduce_norm_kernel<<<M, 256>>>(part, bo + l*DD, h, h,
                                       n2s + l*DD, n2b + l*DD, hn, MN_DD);

        // ffn = gelu(hn @ w1 + b1) (tensor; output rounded)
        launch_mma(hn, w1R + (long long)l*DD*DFF, 0, 0, ffn, 0, 0,
                   b1 + l*DFF, 0, M, DFF, DD, DFF, DFF, 1, 1, 1);

        // FFN2 split-K x4 -> partials; fused reduce + residual + next norm -> h, hn
        launch_mma_split4(ffn, w2R + (long long)l*DFF*DD, part, M, DD, DFF);
        if (l < NLAYER - 1)
            reduce_norm_kernel<<<M, 256>>>(part, b2 + l*DD, h, h,
                                           n1s + (l+1)*DD, n1b + (l+1)*DD, hn, MN_DD);
        else
            reduce_norm_kernel<<<M, 256>>>(part, b2 + l*DD, h, h, fs, fb, hn, MN_DD);
    }

    // logits = hn @ head_w + head_b (tensor, 256-wide tile)
    launch_mma_wide(hn, hwR, out, hb, M, VV, DD, VV, VV);
}